// round 3
// baseline (speedup 1.0000x reference)
#include <cuda_runtime.h>
#include <math.h>

// Problem constants
#define Bn 8
#define C  256
#define CK 32
#define N  4096

// ---------------- scratch (global __device__, no allocs) ----------------
__device__ float d_f[Bn * CK * N];            // f[b][k][n]   4 MB
__device__ float d_g[Bn * CK * N];            // g[b][k][n]   4 MB
__device__ float d_hp[(size_t)Bn * N * C];    // h'[b][n][c] 32 MB (pre-scaled by 1/Z)
__device__ float d_hwT[C * C];                // h_w transposed [c][o]
__device__ float d_m[Bn * N];                 // column max  m_j
__device__ float d_rz[Bn * N];                // 1 / Z_j

// ---------------- transpose h_w: [o][c] -> [c][o] ----------------
__global__ void k_transpose_hw(const float* __restrict__ hw) {
    int idx = blockIdx.x * 256 + threadIdx.x;   // 65536 elements
    int c = idx >> 8, o = idx & 255;
    d_hwT[c * C + o] = hw[o * C + c];
}

// ---------------- f,g projections: out[b][o<32][n] ----------------
// grid (32 nb, 8 b, 2 which), 256 threads
__global__ void k_proj_fg(const float* __restrict__ x,
                          const float* __restrict__ fw, const float* __restrict__ fb,
                          const float* __restrict__ gw, const float* __restrict__ gb) {
    __shared__ float xs[32][128];
    __shared__ float ws[32][32];   // ws[cc][o]
    int nb = blockIdx.x, b = blockIdx.y, which = blockIdx.z;
    const float* w    = which ? gw : fw;
    const float* bias = which ? gb : fb;
    float* o = which ? d_g : d_f;
    int tid = threadIdx.x;
    int oq = tid & 3;       // 4 groups of 8 outputs
    int nq = tid >> 2;      // 64 groups of 2 pixels
    float acc[8][2] = {};

    for (int c0 = 0; c0 < 256; c0 += 32) {
        __syncthreads();
        for (int t = tid; t < 1024; t += 256)
            ((float4*)xs)[t] = ((const float4*)x)[ ((size_t)b * C + c0 + (t >> 5)) * 1024
                                                   + (size_t)nb * 32 + (t & 31) ];
        for (int t = tid; t < 1024; t += 256) {
            int oo = t >> 5, cc = t & 31;
            ws[cc][oo] = w[oo * C + c0 + cc];
        }
        __syncthreads();
#pragma unroll
        for (int k = 0; k < 32; k++) {
            float x0 = xs[k][nq * 2], x1 = xs[k][nq * 2 + 1];
#pragma unroll
            for (int u = 0; u < 8; u++) {
                float wv = ws[k][oq * 8 + u];
                acc[u][0] += wv * x0;
                acc[u][1] += wv * x1;
            }
        }
    }
#pragma unroll
    for (int u = 0; u < 8; u++) {
        int oo = oq * 8 + u;
        float bz = bias[oo];
        size_t base = ((size_t)(b * CK + oo)) * N + nb * 128 + nq * 2;
        o[base]     = acc[u][0] + bz;
        o[base + 1] = acc[u][1] + bz;
    }
}

// ---------------- pass 1: column softmax stats over i ----------------
// grid (32 jb, 8 b), 256 threads. dyn smem = (4096+4096+128*132)*4 = 100352 B
__global__ void k_stats() {
    extern __shared__ float sm[];
    float* sGt = sm;                 // [32][128]  g[k][j]
    float* sFt = sGt + 32 * 128;     // [32][128]  f[k][i]
    float* sS  = sFt + 32 * 128;     // [128][132] S tile (padded)
    int jb = blockIdx.x, b = blockIdx.y;
    int tid = threadIdx.x, ti = tid & 15, tj = tid >> 4;

    // g tile fixed for the whole block
    for (int t = tid; t < 1024; t += 256)
        ((float4*)sGt)[t] = ((const float4*)d_g)[ (size_t)(b * CK + (t >> 5)) * 1024
                                                  + jb * 32 + (t & 31) ];

    float m = -INFINITY, z = 0.f;
    int rj = tid & 127, half = tid >> 7;

    for (int ib = 0; ib < 32; ib++) {
        __syncthreads();
        for (int t = tid; t < 1024; t += 256)
            ((float4*)sFt)[t] = ((const float4*)d_f)[ (size_t)(b * CK + (t >> 5)) * 1024
                                                      + ib * 32 + (t & 31) ];
        __syncthreads();

        float e[8][8];
#pragma unroll
        for (int r = 0; r < 8; r++)
#pragma unroll
            for (int s = 0; s < 8; s++) e[r][s] = 0.f;

#pragma unroll 8
        for (int k = 0; k < 32; k++) {
            float a[8], g[8];
            *(float4*)(a)     = *(float4*)&sFt[k * 128 + ti * 8];
            *(float4*)(a + 4) = *(float4*)&sFt[k * 128 + ti * 8 + 4];
            *(float4*)(g)     = *(float4*)&sGt[k * 128 + tj * 8];
            *(float4*)(g + 4) = *(float4*)&sGt[k * 128 + tj * 8 + 4];
#pragma unroll
            for (int r = 0; r < 8; r++)
#pragma unroll
                for (int s = 0; s < 8; s++) e[r][s] += a[r] * g[s];
        }
#pragma unroll
        for (int r = 0; r < 8; r++) {
            *(float4*)&sS[(ti * 8 + r) * 132 + tj * 8]     = make_float4(e[r][0], e[r][1], e[r][2], e[r][3]);
            *(float4*)&sS[(ti * 8 + r) * 132 + tj * 8 + 4] = make_float4(e[r][4], e[r][5], e[r][6], e[r][7]);
        }
        __syncthreads();

        // online column softmax stats: this thread owns column rj, rows [half*64, half*64+64)
        for (int i = half * 64; i < half * 64 + 64; i++) {
            float v = sS[i * 132 + rj];
            if (v <= m) {
                z += __expf(v - m);
            } else {
                z = z * __expf(m - v) + 1.f;
                m = v;
            }
        }
    }
    __syncthreads();
    if (tid >= 128) { sS[rj] = m; sS[128 + rj] = z; }
    __syncthreads();
    if (tid < 128) {
        float m1 = sS[rj], z1 = sS[128 + rj];
        float nm = fmaxf(m, m1);
        float zz = z * __expf(m - nm) + z1 * __expf(m1 - nm);
        d_m[b * N + jb * 128 + rj]  = nm;
        d_rz[b * N + jb * 128 + rj] = 1.f / zz;
    }
}

// ---------------- h projection, fused with 1/Z scaling: h'[b][n][c] ----------------
// grid (32 nb, 8 b, 2 ch), 256 threads
__global__ void k_proj_h(const float* __restrict__ x, const float* __restrict__ hb) {
    __shared__ float xs[32][128];
    __shared__ float ws[32][128];
    int nb = blockIdx.x, b = blockIdx.y, ch = blockIdx.z;
    int tid = threadIdx.x, tn = tid & 15, tc = tid >> 4;
    float acc[8][8] = {};

    for (int c0 = 0; c0 < 256; c0 += 32) {
        __syncthreads();
        for (int t = tid; t < 1024; t += 256) {
            ((float4*)xs)[t] = ((const float4*)x)[ ((size_t)b * C + c0 + (t >> 5)) * 1024
                                                   + (size_t)nb * 32 + (t & 31) ];
            ((float4*)ws)[t] = ((const float4*)d_hwT)[ (size_t)(c0 + (t >> 5)) * 64
                                                       + ch * 32 + (t & 31) ];
        }
        __syncthreads();
#pragma unroll 8
        for (int k = 0; k < 32; k++) {
            float a[8], w[8];
            *(float4*)(a)     = *(float4*)&xs[k][tn * 8];
            *(float4*)(a + 4) = *(float4*)&xs[k][tn * 8 + 4];
            *(float4*)(w)     = *(float4*)&ws[k][tc * 8];
            *(float4*)(w + 4) = *(float4*)&ws[k][tc * 8 + 4];
#pragma unroll
            for (int r = 0; r < 8; r++)
#pragma unroll
                for (int s = 0; s < 8; s++) acc[r][s] += a[r] * w[s];
        }
    }
#pragma unroll
    for (int r = 0; r < 8; r++) {
        int n = nb * 128 + tn * 8 + r;
        float rz = d_rz[b * N + n];
        size_t base = ((size_t)b * N + n) * C + ch * 128 + tc * 8;
        float4 o0, o1;
        o0.x = (acc[r][0] + hb[ch * 128 + tc * 8 + 0]) * rz;
        o0.y = (acc[r][1] + hb[ch * 128 + tc * 8 + 1]) * rz;
        o0.z = (acc[r][2] + hb[ch * 128 + tc * 8 + 2]) * rz;
        o0.w = (acc[r][3] + hb[ch * 128 + tc * 8 + 3]) * rz;
        o1.x = (acc[r][4] + hb[ch * 128 + tc * 8 + 4]) * rz;
        o1.y = (acc[r][5] + hb[ch * 128 + tc * 8 + 5]) * rz;
        o1.z = (acc[r][6] + hb[ch * 128 + tc * 8 + 6]) * rz;
        o1.w = (acc[r][7] + hb[ch * 128 + tc * 8 + 7]) * rz;
        *(float4*)&d_hp[base]     = o0;
        *(float4*)&d_hp[base + 4] = o1;
    }
}

// ---------------- pass 2: O^T[i][c] = sum_j exp(S[i][j]-m_j) * h'[j][c]; out = O + x ----------------
// grid (32 ib, 8 b, 2 ch), 256 threads. dyn smem = (4096+4096+128+16384+16384)*4 = 164352 B
__global__ void k_out(const float* __restrict__ x, float* __restrict__ out) {
    extern __shared__ float sm[];
    float* sFt = sm;                 // [32][128] f[k][i]
    float* sGt = sFt + 4096;         // [32][128] g[k][j]
    float* sM  = sGt + 4096;         // [128]
    float* sEt = sM + 128;           // [128][128] E^T[j][i]
    float* sH  = sEt + 16384;        // [128][128] h'[j][c]
    int ib = blockIdx.x, b = blockIdx.y, ch = blockIdx.z;
    int tid = threadIdx.x, ti = tid & 15, tj = tid >> 4;

    // f tile fixed for the whole block (i-range fixed)
    for (int t = tid; t < 1024; t += 256)
        ((float4*)sFt)[t] = ((const float4*)d_f)[ (size_t)(b * CK + (t >> 5)) * 1024
                                                  + ib * 32 + (t & 31) ];
    float acc[8][8] = {};

    for (int jb = 0; jb < 32; jb++) {
        __syncthreads();
        for (int t = tid; t < 1024; t += 256)
            ((float4*)sGt)[t] = ((const float4*)d_g)[ (size_t)(b * CK + (t >> 5)) * 1024
                                                      + jb * 32 + (t & 31) ];
        if (tid < 128) sM[tid] = d_m[b * N + jb * 128 + tid];
        for (int t = tid; t < 4096; t += 256)
            ((float4*)sH)[t] = ((const float4*)d_hp)[ ((size_t)b * N + jb * 128 + (t >> 5)) * 64
                                                      + ch * 32 + (t & 31) ];
        __syncthreads();

        // S tile (K=32)
        float e[8][8];
#pragma unroll
        for (int r = 0; r < 8; r++)
#pragma unroll
            for (int s = 0; s < 8; s++) e[r][s] = 0.f;
#pragma unroll 8
        for (int k = 0; k < 32; k++) {
            float a[8], g[8];
            *(float4*)(a)     = *(float4*)&sFt[k * 128 + ti * 8];
            *(float4*)(a + 4) = *(float4*)&sFt[k * 128 + ti * 8 + 4];
            *(float4*)(g)     = *(float4*)&sGt[k * 128 + tj * 8];
            *(float4*)(g + 4) = *(float4*)&sGt[k * 128 + tj * 8 + 4];
#pragma unroll
            for (int r = 0; r < 8; r++)
#pragma unroll
                for (int s = 0; s < 8; s++) e[r][s] += a[r] * g[s];
        }
        // E^T[j][i] = exp(S - m_j)
#pragma unroll
        for (int s = 0; s < 8; s++) {
            float mj = sM[tj * 8 + s];
            float4 v0 = make_float4(__expf(e[0][s] - mj), __expf(e[1][s] - mj),
                                    __expf(e[2][s] - mj), __expf(e[3][s] - mj));
            float4 v1 = make_float4(__expf(e[4][s] - mj), __expf(e[5][s] - mj),
                                    __expf(e[6][s] - mj), __expf(e[7][s] - mj));
            *(float4*)&sEt[(tj * 8 + s) * 128 + ti * 8]     = v0;
            *(float4*)&sEt[(tj * 8 + s) * 128 + ti * 8 + 4] = v1;
        }
        __syncthreads();

        // O^T tile += E^T(k=j) x h'(k=j): K=128
#pragma unroll 4
        for (int k = 0; k < 128; k++) {
            float a[8], h[8];
            *(float4*)(a)     = *(float4*)&sEt[k * 128 + ti * 8];
            *(float4*)(a + 4) = *(float4*)&sEt[k * 128 + ti * 8 + 4];
            *(float4*)(h)     = *(float4*)&sH[k * 128 + tj * 8];
            *(float4*)(h + 4) = *(float4*)&sH[k * 128 + tj * 8 + 4];
#pragma unroll
            for (int r = 0; r < 8; r++)
#pragma unroll
                for (int s = 0; s < 8; s++) acc[r][s] += a[r] * h[s];
        }
    }

    // epilogue: out[b][c][i] = O + x  (gamma = 1)
#pragma unroll
    for (int s = 0; s < 8; s++) {
        int c = ch * 128 + tj * 8 + s;
        size_t base = ((size_t)b * C + c) * N + ib * 128 + ti * 8;
        float4 x0 = *(const float4*)&x[base];
        float4 x1 = *(const float4*)&x[base + 4];
        float4 o0 = make_float4(acc[0][s] + x0.x, acc[1][s] + x0.y,
                                acc[2][s] + x0.z, acc[3][s] + x0.w);
        float4 o1 = make_float4(acc[4][s] + x1.x, acc[5][s] + x1.y,
                                acc[6][s] + x1.z, acc[7][s] + x1.w);
        *(float4*)&out[base]     = o0;
        *(float4*)&out[base + 4] = o1;
    }
}

// ---------------- launch ----------------
extern "C" void kernel_launch(void* const* d_in, const int* in_sizes, int n_in,
                              void* d_out, int out_size) {
    const float* x  = (const float*)d_in[0];
    const float* fw = (const float*)d_in[1];
    const float* fb = (const float*)d_in[2];
    const float* gw = (const float*)d_in[3];
    const float* gb = (const float*)d_in[4];
    const float* hw = (const float*)d_in[5];
    const float* hb = (const float*)d_in[6];
    float* out = (float*)d_out;

    const int SMEM_B = (4096 + 4096 + 128 * 132) * 4;                    // 100352
    const int SMEM_C = (4096 + 4096 + 128 + 16384 + 16384) * 4;         // 164352
    cudaFuncSetAttribute(k_stats, cudaFuncAttributeMaxDynamicSharedMemorySize, SMEM_B);
    cudaFuncSetAttribute(k_out,   cudaFuncAttributeMaxDynamicSharedMemorySize, SMEM_C);

    k_transpose_hw<<<256, 256>>>(hw);
    k_proj_fg<<<dim3(32, 8, 2), 256>>>(x, fw, fb, gw, gb);
    k_stats<<<dim3(32, 8), 256, SMEM_B>>>();
    k_proj_h<<<dim3(32, 8, 2), 256>>>(x, hb);
    k_out<<<dim3(32, 8, 2), 256, SMEM_C>>>(x, out);
}

// round 5
// speedup vs baseline: 2.2984x; 2.2984x over previous
#include <cuda_runtime.h>
#include <cuda_bf16.h>
#include <cstdint>
#include <math.h>

#define Bn 8
#define C  256
#define N  4096

// ---------------- scratch ----------------
__device__ __nv_bfloat16 d_fp[Bn * N * 64];            // f packed [b][n][hi k0..31 | lo k0..31]
__device__ __nv_bfloat16 d_gp[Bn * N * 64];            // g packed
__device__ __nv_bfloat16 d_hTh[(size_t)Bn * C * N];    // h' hi [b][c][j] (pre-scaled 1/Z)
__device__ __nv_bfloat16 d_hTl[(size_t)Bn * C * N];    // h' lo
__device__ float d_hwT[C * C];
__device__ float d_rz[Bn * N];

// ---------------- helpers ----------------
__device__ __forceinline__ uint32_t smem_u32(const void* p) {
    uint32_t a;
    asm("{ .reg .u64 t; cvta.to.shared.u64 t, %1; cvt.u32.u64 %0, t; }" : "=r"(a) : "l"(p));
    return a;
}
__device__ __forceinline__ void ldsm4(uint32_t* r, uint32_t a) {
    asm volatile("ldmatrix.sync.aligned.m8n8.x4.shared.b16 {%0,%1,%2,%3}, [%4];"
        : "=r"(r[0]), "=r"(r[1]), "=r"(r[2]), "=r"(r[3]) : "r"(a));
}
__device__ __forceinline__ void ldsm2(uint32_t* r, uint32_t a) {
    asm volatile("ldmatrix.sync.aligned.m8n8.x2.shared.b16 {%0,%1}, [%2];"
        : "=r"(r[0]), "=r"(r[1]) : "r"(a));
}
__device__ __forceinline__ void mma_bf16(float* d, const uint32_t* a, const uint32_t* b) {
    asm volatile("mma.sync.aligned.m16n8k16.row.col.f32.bf16.bf16.f32 "
        "{%0,%1,%2,%3}, {%4,%5,%6,%7}, {%8,%9}, {%0,%1,%2,%3};"
        : "+f"(d[0]), "+f"(d[1]), "+f"(d[2]), "+f"(d[3])
        : "r"(a[0]), "r"(a[1]), "r"(a[2]), "r"(a[3]), "r"(b[0]), "r"(b[1]));
}
__device__ __forceinline__ float trunc_hi(float v) {
    return __uint_as_float(__float_as_uint(v) & 0xFFFF0000u);
}
__device__ __forceinline__ uint32_t pack2(float lo_e, float hi_e) {  // low half = lo_e
    uint32_t r;
    asm("cvt.rn.satfinite.bf16x2.f32 %0, %1, %2;" : "=r"(r) : "f"(hi_e), "f"(lo_e));
    return r;
}
__device__ __forceinline__ void split2(float v, __nv_bfloat16& h, __nv_bfloat16& l) {
    unsigned int bi = __float_as_uint(v);
    h = __ushort_as_bfloat16((unsigned short)(bi >> 16));
    l = __float2bfloat16(v - __uint_as_float(bi & 0xFFFF0000u));
}

// ---------------- transpose h_w ----------------
__global__ void k_transpose_hw(const float* __restrict__ hw) {
    int idx = blockIdx.x * 256 + threadIdx.x;
    d_hwT[(idx & 255) * C + (idx >> 8)] = hw[idx];
}

// ---------------- f,g projections -> packed bf16 hi/lo ----------------
__global__ void k_proj_fg(const float* __restrict__ x,
                          const float* __restrict__ fw, const float* __restrict__ fb,
                          const float* __restrict__ gw, const float* __restrict__ gb) {
    __shared__ float xs[32][128];
    __shared__ float ws[32][32];
    int nb = blockIdx.x, b = blockIdx.y, which = blockIdx.z;
    const float* w    = which ? gw : fw;
    const float* bias = which ? gb : fb;
    __nv_bfloat16* o  = which ? d_gp : d_fp;
    int tid = threadIdx.x, oq = tid & 3, nq = tid >> 2;
    float acc[8][2] = {};
    for (int c0 = 0; c0 < 256; c0 += 32) {
        __syncthreads();
        for (int t = tid; t < 1024; t += 256)
            ((float4*)xs)[t] = ((const float4*)x)[((size_t)b * C + c0 + (t >> 5)) * 1024 + (size_t)nb * 32 + (t & 31)];
        for (int t = tid; t < 1024; t += 256)
            ws[t & 31][t >> 5] = w[(t >> 5) * C + c0 + (t & 31)];
        __syncthreads();
#pragma unroll
        for (int k = 0; k < 32; k++) {
            float x0 = xs[k][nq * 2], x1 = xs[k][nq * 2 + 1];
#pragma unroll
            for (int u = 0; u < 8; u++) {
                float wv = ws[k][oq * 8 + u];
                acc[u][0] += wv * x0;
                acc[u][1] += wv * x1;
            }
        }
    }
    int n0 = nb * 128 + nq * 2;
    size_t r0 = (size_t)(b * N + n0) * 64;
#pragma unroll
    for (int u = 0; u < 8; u++) {
        int oo = oq * 8 + u;
        float bz = bias[oo];
        __nv_bfloat16 h, l;
        split2(acc[u][0] + bz, h, l);  o[r0 + oo] = h;       o[r0 + 32 + oo] = l;
        split2(acc[u][1] + bz, h, l);  o[r0 + 64 + oo] = h;  o[r0 + 96 + oo] = l;
    }
}

// ---------------- pass 1: Z_j via HMMA (S^T tiles) ----------------
// grid (32 jb, 8 b), 256 threads, dyn smem 41984
__global__ __launch_bounds__(256, 1) void k_zsum() {
    extern __shared__ char sm[];
    const int SGH = 0, SGL = 10240, SFH = 20480, SFL = 30720, SZ = 40960;
    uint32_t sb = smem_u32(sm);
    int tid = threadIdx.x, lane = tid & 31, w = tid >> 5;
    int jb = blockIdx.x, b = blockIdx.y;
    int wj = w & 3, wi2 = w >> 2;

    for (int t = tid; t < 1024; t += 256) {
        int row = t >> 3, p = t & 7;
        uint4 v = ((const uint4*)d_gp)[(size_t)(b * N + jb * 128 + row) * 8 + p];
        *(uint4*)(sm + (p < 4 ? SGH + row * 80 + p * 16 : SGL + row * 80 + (p - 4) * 16)) = v;
    }
    float zacc[4] = {0.f, 0.f, 0.f, 0.f};

    for (int ibt = 0; ibt < 32; ibt++) {
        __syncthreads();
        for (int t = tid; t < 1024; t += 256) {
            int row = t >> 3, p = t & 7;
            uint4 v = ((const uint4*)d_fp)[(size_t)(b * N + ibt * 128 + row) * 8 + p];
            *(uint4*)(sm + (p < 4 ? SFH + row * 80 + p * 16 : SFL + row * 80 + (p - 4) * 16)) = v;
        }
        __syncthreads();
        float as[2][8][4] = {};
#pragma unroll
        for (int term = 0; term < 3; term++) {
            int Ab = (term == 2) ? SGL : SGH;   // A parts: gh, gh, gl
            int Bb = (term == 1) ? SFL : SFH;   // B parts: fh, fl, fh
#pragma unroll
            for (int k16 = 0; k16 < 2; k16++) {
                uint32_t a0[4], a1[4];
                ldsm4(a0, sb + Ab + (wj * 32 +      (lane & 15)) * 80 + k16 * 32 + (lane >> 4) * 16);
                ldsm4(a1, sb + Ab + (wj * 32 + 16 + (lane & 15)) * 80 + k16 * 32 + (lane >> 4) * 16);
#pragma unroll
                for (int n8 = 0; n8 < 8; n8++) {
                    uint32_t bb[2];
                    ldsm2(bb, sb + Bb + (wi2 * 64 + n8 * 8 + (lane & 7)) * 80 + k16 * 32 + ((lane >> 3) & 1) * 16);
                    mma_bf16(as[0][n8], a0, bb);
                    mma_bf16(as[1][n8], a1, bb);
                }
            }
        }
#pragma unroll
        for (int mh = 0; mh < 2; mh++)
#pragma unroll
            for (int n8 = 0; n8 < 8; n8++) {
                zacc[mh * 2 + 0] += __expf(as[mh][n8][0]) + __expf(as[mh][n8][1]);
                zacc[mh * 2 + 1] += __expf(as[mh][n8][2]) + __expf(as[mh][n8][3]);
            }
    }
#pragma unroll
    for (int m = 0; m < 4; m++) {
        float v = zacc[m];
        v += __shfl_xor_sync(0xffffffffu, v, 1);
        v += __shfl_xor_sync(0xffffffffu, v, 2);
        if ((lane & 3) == 0) {
            int jloc = wj * 32 + (m >> 1) * 16 + (m & 1) * 8 + (lane >> 2);
            *(float*)(sm + SZ + (wi2 * 128 + jloc) * 4) = v;
        }
    }
    __syncthreads();
    if (tid < 128) {
        float z = *(float*)(sm + SZ + tid * 4) + *(float*)(sm + SZ + (128 + tid) * 4);
        d_rz[b * N + jb * 128 + tid] = 1.f / z;
    }
}

// ---------------- h projection -> h'T hi/lo [b][c][j], pre-scaled 1/Z ----------------
__global__ void k_proj_h(const float* __restrict__ x, const float* __restrict__ hb) {
    __shared__ float xs[32][128];
    __shared__ float ws[32][128];
    int nb = blockIdx.x, b = blockIdx.y, ch = blockIdx.z;
    int tid = threadIdx.x, tn = tid & 15, tc = tid >> 4;
    float acc[8][8] = {};
    for (int c0 = 0; c0 < 256; c0 += 32) {
        __syncthreads();
        for (int t = tid; t < 1024; t += 256) {
            ((float4*)xs)[t] = ((const float4*)x)[((size_t)b * C + c0 + (t >> 5)) * 1024 + (size_t)nb * 32 + (t & 31)];
            ((float4*)ws)[t] = ((const float4*)d_hwT)[(size_t)(c0 + (t >> 5)) * 64 + ch * 32 + (t & 31)];
        }
        __syncthreads();
#pragma unroll 8
        for (int k = 0; k < 32; k++) {
            float a[8], wv[8];
            *(float4*)(a)      = *(float4*)&xs[k][tn * 8];
            *(float4*)(a + 4)  = *(float4*)&xs[k][tn * 8 + 4];
            *(float4*)(wv)     = *(float4*)&ws[k][tc * 8];
            *(float4*)(wv + 4) = *(float4*)&ws[k][tc * 8 + 4];
#pragma unroll
            for (int r = 0; r < 8; r++)
#pragma unroll
                for (int s = 0; s < 8; s++) acc[r][s] += a[r] * wv[s];
        }
    }
    float rz[8];
#pragma unroll
    for (int r = 0; r < 8; r++) rz[r] = d_rz[b * N + nb * 128 + tn * 8 + r];
#pragma unroll
    for (int s = 0; s < 8; s++) {
        int c = ch * 128 + tc * 8 + s;
        float bz = hb[c];
        __nv_bfloat16 hv[8], lv[8];
#pragma unroll
        for (int r = 0; r < 8; r++) split2((acc[r][s] + bz) * rz[r], hv[r], lv[r]);
        size_t base = ((size_t)b * C + c) * N + nb * 128 + tn * 8;
        *(uint4*)&d_hTh[base] = *(uint4*)hv;
        *(uint4*)&d_hTl[base] = *(uint4*)lv;
    }
}

// ---------------- pass 2: S-HMMA -> exp -> E -> O-HMMA, out = O + x ----------------
// grid (32 ib, 8 b, 2 ch), 256 threads, dyn smem 180224
__global__ __launch_bounds__(256, 1) void k_out(const float* __restrict__ x, float* __restrict__ out) {
    extern __shared__ char sm[];
    const int SFH = 0, SFL = 10240, SGH = 20480, SGL = 30720;
    const int SEH = 40960, SEL = 75776, SHH = 110592, SHL = 145408;
    uint32_t sb = smem_u32(sm);
    int tid = threadIdx.x, lane = tid & 31, w = tid >> 5;
    int ib = blockIdx.x, b = blockIdx.y, ch = blockIdx.z;
    int wa = w & 3, wb = w >> 2;   // S: i-quarter / j-half;  O: c-quarter / i-half

    for (int t = tid; t < 1024; t += 256) {
        int row = t >> 3, p = t & 7;
        uint4 v = ((const uint4*)d_fp)[(size_t)(b * N + ib * 128 + row) * 8 + p];
        *(uint4*)(sm + (p < 4 ? SFH + row * 80 + p * 16 : SFL + row * 80 + (p - 4) * 16)) = v;
    }
    float ao[2][8][4] = {};

    for (int jb = 0; jb < 32; jb++) {
        __syncthreads();
        for (int t = tid; t < 1024; t += 256) {
            int row = t >> 3, p = t & 7;
            uint4 v = ((const uint4*)d_gp)[(size_t)(b * N + jb * 128 + row) * 8 + p];
            *(uint4*)(sm + (p < 4 ? SGH + row * 80 + p * 16 : SGL + row * 80 + (p - 4) * 16)) = v;
        }
        for (int t = tid; t < 2048; t += 256) {
            int row = t >> 4, u = t & 15;
            size_t src = (size_t)(b * C + ch * 128 + row) * 512 + jb * 16 + u;
            *(uint4*)(sm + SHH + row * 272 + u * 16) = ((const uint4*)d_hTh)[src];
            *(uint4*)(sm + SHL + row * 272 + u * 16) = ((const uint4*)d_hTl)[src];
        }
        __syncthreads();

        // --- S tile: rows i = wa*32.., cols j = wb*64.. ---
        float as[2][8][4] = {};
#pragma unroll
        for (int term = 0; term < 3; term++) {
            int Ab = (term == 2) ? SFL : SFH;
            int Bb = (term == 1) ? SGL : SGH;
#pragma unroll
            for (int k16 = 0; k16 < 2; k16++) {
                uint32_t a0[4], a1[4];
                ldsm4(a0, sb + Ab + (wa * 32 +      (lane & 15)) * 80 + k16 * 32 + (lane >> 4) * 16);
                ldsm4(a1, sb + Ab + (wa * 32 + 16 + (lane & 15)) * 80 + k16 * 32 + (lane >> 4) * 16);
#pragma unroll
                for (int n8 = 0; n8 < 8; n8++) {
                    uint32_t bb[2];
                    ldsm2(bb, sb + Bb + (wb * 64 + n8 * 8 + (lane & 7)) * 80 + k16 * 32 + ((lane >> 3) & 1) * 16);
                    mma_bf16(as[0][n8], a0, bb);
                    mma_bf16(as[1][n8], a1, bb);
                }
            }
        }
        // --- exp + split -> sE ---
#pragma unroll
        for (int mh = 0; mh < 2; mh++)
#pragma unroll
            for (int n8 = 0; n8 < 8; n8++) {
                int irow = wa * 32 + mh * 16 + (lane >> 2);
                int jcol = wb * 64 + n8 * 8 + 2 * (lane & 3);
                float e0 = __expf(as[mh][n8][0]), e1 = __expf(as[mh][n8][1]);
                float h0 = trunc_hi(e0), h1 = trunc_hi(e1);
                *(uint32_t*)(sm + SEH + irow * 272 + jcol * 2) = pack2(h0, h1);
                *(uint32_t*)(sm + SEL + irow * 272 + jcol * 2) = pack2(e0 - h0, e1 - h1);
                e0 = __expf(as[mh][n8][2]); e1 = __expf(as[mh][n8][3]);
                h0 = trunc_hi(e0); h1 = trunc_hi(e1);
                *(uint32_t*)(sm + SEH + (irow + 8) * 272 + jcol * 2) = pack2(h0, h1);
                *(uint32_t*)(sm + SEL + (irow + 8) * 272 + jcol * 2) = pack2(e0 - h0, e1 - h1);
            }
        __syncthreads();

        // --- O tile: A = h' rows c (wa*32..), B = E rows i (wb*64..), k = j 128 ---
#pragma unroll
        for (int term = 0; term < 3; term++) {
            int Ab = (term == 2) ? SHL : SHH;   // A: Hh, Hh, Hl
            int Bb = (term == 1) ? SEL : SEH;   // B: Eh, El, Eh
#pragma unroll
            for (int k16 = 0; k16 < 8; k16++) {
                uint32_t a0[4], a1[4];
                ldsm4(a0, sb + Ab + (wa * 32 +      (lane & 15)) * 272 + k16 * 32 + (lane >> 4) * 16);
                ldsm4(a1, sb + Ab + (wa * 32 + 16 + (lane & 15)) * 272 + k16 * 32 + (lane >> 4) * 16);
#pragma unroll
                for (int n8 = 0; n8 < 8; n8++) {
                    uint32_t bb[2];
                    ldsm2(bb, sb + Bb + (wb * 64 + n8 * 8 + (lane & 7)) * 272 + k16 * 32 + ((lane >> 3) & 1) * 16);
                    mma_bf16(ao[0][n8], a0, bb);
                    mma_bf16(ao[1][n8], a1, bb);
                }
            }
        }
    }

    // epilogue: out[b][c][i] = O + x
#pragma unroll
    for (int mh = 0; mh < 2; mh++)
#pragma unroll
        for (int n8 = 0; n8 < 8; n8++) {
            int c = ch * 128 + wa * 32 + mh * 16 + (lane >> 2);
            int icol = ib * 128 + wb * 64 + n8 * 8 + 2 * (lane & 3);
            size_t idx = (size_t)(b * C + c) * N + icol;
            float2 xv = *(const float2*)&x[idx];
            *(float2*)&out[idx] = make_float2(ao[mh][n8][0] + xv.x, ao[mh][n8][1] + xv.y);
            idx += (size_t)8 * N;
            xv = *(const float2*)&x[idx];
            *(float2*)&out[idx] = make_float2(ao[mh][n8][2] + xv.x, ao[mh][n8][3] + xv.y);
        }
}

// ---------------- launch ----------------
extern "C" void kernel_launch(void* const* d_in, const int* in_sizes, int n_in,
                              void* d_out, int out_size) {
    const float* x  = (const float*)d_in[0];
    const float* fw = (const float*)d_in[1];
    const float* fb = (const float*)d_in[2];
    const float* gw = (const float*)d_in[3];
    const float* gb = (const float*)d_in[4];
    const float* hw = (const float*)d_in[5];
    const float* hb = (const float*)d_in[6];
    float* out = (float*)d_out;

    const int SM_Z = 41984;
    const int SM_O = 180224;
    cudaFuncSetAttribute(k_zsum, cudaFuncAttributeMaxDynamicSharedMemorySize, SM_Z);
    cudaFuncSetAttribute(k_out,  cudaFuncAttributeMaxDynamicSharedMemorySize, SM_O);

    k_transpose_hw<<<256, 256>>>(hw);
    k_proj_fg<<<dim3(32, 8, 2), 256>>>(x, fw, fb, gw, gb);
    k_zsum<<<dim3(32, 8), 256, SM_Z>>>();
    k_proj_h<<<dim3(32, 8, 2), 256>>>(x, hb);
    k_out<<<dim3(32, 8, 2), 256, SM_O>>>(x, out);
}

// round 6
// speedup vs baseline: 3.1889x; 1.3874x over previous
#include <cuda_runtime.h>
#include <cuda_bf16.h>
#include <cstdint>
#include <math.h>

#define Bn 8
#define C  256
#define N  4096

// ---------------- scratch ----------------
__device__ __nv_bfloat16 d_fp[Bn * N * 64];            // f packed [b][n][hi k0..31 | lo k0..31]
__device__ __nv_bfloat16 d_gp[Bn * N * 64];            // g packed
__device__ __nv_bfloat16 d_hTh[(size_t)Bn * C * N];    // h' RN bf16 [b][c][j] (pre-scaled 1/Z)
__device__ float d_hwT[C * C];
__device__ float d_rz[Bn * N];

// ---------------- helpers ----------------
__device__ __forceinline__ uint32_t smem_u32(const void* p) {
    uint32_t a;
    asm("{ .reg .u64 t; cvta.to.shared.u64 t, %1; cvt.u32.u64 %0, t; }" : "=r"(a) : "l"(p));
    return a;
}
__device__ __forceinline__ void ldsm4(uint32_t* r, uint32_t a) {
    asm volatile("ldmatrix.sync.aligned.m8n8.x4.shared.b16 {%0,%1,%2,%3}, [%4];"
        : "=r"(r[0]), "=r"(r[1]), "=r"(r[2]), "=r"(r[3]) : "r"(a));
}
__device__ __forceinline__ void ldsm2(uint32_t* r, uint32_t a) {
    asm volatile("ldmatrix.sync.aligned.m8n8.x2.shared.b16 {%0,%1}, [%2];"
        : "=r"(r[0]), "=r"(r[1]) : "r"(a));
}
__device__ __forceinline__ void mma_bf16(float* d, const uint32_t* a, const uint32_t* b) {
    asm volatile("mma.sync.aligned.m16n8k16.row.col.f32.bf16.bf16.f32 "
        "{%0,%1,%2,%3}, {%4,%5,%6,%7}, {%8,%9}, {%0,%1,%2,%3};"
        : "+f"(d[0]), "+f"(d[1]), "+f"(d[2]), "+f"(d[3])
        : "r"(a[0]), "r"(a[1]), "r"(a[2]), "r"(a[3]), "r"(b[0]), "r"(b[1]));
}
__device__ __forceinline__ uint32_t pack2(float lo_e, float hi_e) {  // low half = lo_e, RN
    uint32_t r;
    asm("cvt.rn.satfinite.bf16x2.f32 %0, %1, %2;" : "=r"(r) : "f"(hi_e), "f"(lo_e));
    return r;
}
// round-to-nearest split (zero-mean lo)
__device__ __forceinline__ void split2(float v, __nv_bfloat16& h, __nv_bfloat16& l) {
    h = __float2bfloat16(v);
    l = __float2bfloat16(v - __bfloat162float(h));
}

// ---------------- transpose h_w ----------------
__global__ void k_transpose_hw(const float* __restrict__ hw) {
    int idx = blockIdx.x * 256 + threadIdx.x;
    d_hwT[(idx & 255) * C + (idx >> 8)] = hw[idx];
}

// ---------------- f,g projections -> packed bf16 hi/lo (RN) ----------------
__global__ void k_proj_fg(const float* __restrict__ x,
                          const float* __restrict__ fw, const float* __restrict__ fb,
                          const float* __restrict__ gw, const float* __restrict__ gb) {
    __shared__ float xs[32][128];
    __shared__ float ws[32][32];
    int nb = blockIdx.x, b = blockIdx.y, which = blockIdx.z;
    const float* w    = which ? gw : fw;
    const float* bias = which ? gb : fb;
    __nv_bfloat16* o  = which ? d_gp : d_fp;
    int tid = threadIdx.x, oq = tid & 3, nq = tid >> 2;
    float acc[8][2] = {};
    for (int c0 = 0; c0 < 256; c0 += 32) {
        __syncthreads();
        for (int t = tid; t < 1024; t += 256)
            ((float4*)xs)[t] = ((const float4*)x)[((size_t)b * C + c0 + (t >> 5)) * 1024 + (size_t)nb * 32 + (t & 31)];
        for (int t = tid; t < 1024; t += 256)
            ws[t & 31][t >> 5] = w[(t >> 5) * C + c0 + (t & 31)];
        __syncthreads();
#pragma unroll
        for (int k = 0; k < 32; k++) {
            float x0 = xs[k][nq * 2], x1 = xs[k][nq * 2 + 1];
#pragma unroll
            for (int u = 0; u < 8; u++) {
                float wv = ws[k][oq * 8 + u];
                acc[u][0] += wv * x0;
                acc[u][1] += wv * x1;
            }
        }
    }
    int n0 = nb * 128 + nq * 2;
    size_t r0 = (size_t)(b * N + n0) * 64;
#pragma unroll
    for (int u = 0; u < 8; u++) {
        int oo = oq * 8 + u;
        float bz = bias[oo];
        __nv_bfloat16 h, l;
        split2(acc[u][0] + bz, h, l);  o[r0 + oo] = h;       o[r0 + 32 + oo] = l;
        split2(acc[u][1] + bz, h, l);  o[r0 + 64 + oo] = h;  o[r0 + 96 + oo] = l;
    }
}

// ---------------- pass 1: Z_j via HMMA (S^T tiles) ----------------
// grid (32 jb, 8 b), 256 threads, dyn smem 41984
__global__ __launch_bounds__(256, 1) void k_zsum() {
    extern __shared__ char sm[];
    const int SGH = 0, SGL = 10240, SFH = 20480, SFL = 30720, SZ = 40960;
    uint32_t sb = smem_u32(sm);
    int tid = threadIdx.x, lane = tid & 31, w = tid >> 5;
    int jb = blockIdx.x, b = blockIdx.y;
    int wj = w & 3, wi2 = w >> 2;

    for (int t = tid; t < 1024; t += 256) {
        int row = t >> 3, p = t & 7;
        uint4 v = ((const uint4*)d_gp)[(size_t)(b * N + jb * 128 + row) * 8 + p];
        *(uint4*)(sm + (p < 4 ? SGH + row * 80 + p * 16 : SGL + row * 80 + (p - 4) * 16)) = v;
    }
    float zacc[4] = {0.f, 0.f, 0.f, 0.f};

    for (int ibt = 0; ibt < 32; ibt++) {
        __syncthreads();
        for (int t = tid; t < 1024; t += 256) {
            int row = t >> 3, p = t & 7;
            uint4 v = ((const uint4*)d_fp)[(size_t)(b * N + ibt * 128 + row) * 8 + p];
            *(uint4*)(sm + (p < 4 ? SFH + row * 80 + p * 16 : SFL + row * 80 + (p - 4) * 16)) = v;
        }
        __syncthreads();
        float as[2][8][4] = {};
#pragma unroll
        for (int term = 0; term < 3; term++) {
            int Ab = (term == 2) ? SGL : SGH;   // A parts: gh, gh, gl
            int Bb = (term == 1) ? SFL : SFH;   // B parts: fh, fl, fh
#pragma unroll
            for (int k16 = 0; k16 < 2; k16++) {
                uint32_t a0[4], a1[4];
                ldsm4(a0, sb + Ab + (wj * 32 +      (lane & 15)) * 80 + k16 * 32 + (lane >> 4) * 16);
                ldsm4(a1, sb + Ab + (wj * 32 + 16 + (lane & 15)) * 80 + k16 * 32 + (lane >> 4) * 16);
#pragma unroll
                for (int n8 = 0; n8 < 8; n8++) {
                    uint32_t bb[2];
                    ldsm2(bb, sb + Bb + (wi2 * 64 + n8 * 8 + (lane & 7)) * 80 + k16 * 32 + ((lane >> 3) & 1) * 16);
                    mma_bf16(as[0][n8], a0, bb);
                    mma_bf16(as[1][n8], a1, bb);
                }
            }
        }
#pragma unroll
        for (int mh = 0; mh < 2; mh++)
#pragma unroll
            for (int n8 = 0; n8 < 8; n8++) {
                zacc[mh * 2 + 0] += __expf(as[mh][n8][0]) + __expf(as[mh][n8][1]);
                zacc[mh * 2 + 1] += __expf(as[mh][n8][2]) + __expf(as[mh][n8][3]);
            }
    }
#pragma unroll
    for (int m = 0; m < 4; m++) {
        float v = zacc[m];
        v += __shfl_xor_sync(0xffffffffu, v, 1);
        v += __shfl_xor_sync(0xffffffffu, v, 2);
        if ((lane & 3) == 0) {
            int jloc = wj * 32 + (m >> 1) * 16 + (m & 1) * 8 + (lane >> 2);
            *(float*)(sm + SZ + (wi2 * 128 + jloc) * 4) = v;
        }
    }
    __syncthreads();
    if (tid < 128) {
        float z = *(float*)(sm + SZ + tid * 4) + *(float*)(sm + SZ + (128 + tid) * 4);
        d_rz[b * N + jb * 128 + tid] = 1.f / z;
    }
}

// ---------------- h projection -> h' RN bf16 [b][c][j], pre-scaled 1/Z ----------------
__global__ void k_proj_h(const float* __restrict__ x, const float* __restrict__ hb) {
    __shared__ float xs[32][128];
    __shared__ float ws[32][128];
    int nb = blockIdx.x, b = blockIdx.y, ch = blockIdx.z;
    int tid = threadIdx.x, tn = tid & 15, tc = tid >> 4;
    float acc[8][8] = {};
    for (int c0 = 0; c0 < 256; c0 += 32) {
        __syncthreads();
        for (int t = tid; t < 1024; t += 256) {
            ((float4*)xs)[t] = ((const float4*)x)[((size_t)b * C + c0 + (t >> 5)) * 1024 + (size_t)nb * 32 + (t & 31)];
            ((float4*)ws)[t] = ((const float4*)d_hwT)[(size_t)(c0 + (t >> 5)) * 64 + ch * 32 + (t & 31)];
        }
        __syncthreads();
#pragma unroll 8
        for (int k = 0; k < 32; k++) {
            float a[8], wv[8];
            *(float4*)(a)      = *(float4*)&xs[k][tn * 8];
            *(float4*)(a + 4)  = *(float4*)&xs[k][tn * 8 + 4];
            *(float4*)(wv)     = *(float4*)&ws[k][tc * 8];
            *(float4*)(wv + 4) = *(float4*)&ws[k][tc * 8 + 4];
#pragma unroll
            for (int r = 0; r < 8; r++)
#pragma unroll
                for (int s = 0; s < 8; s++) acc[r][s] += a[r] * wv[s];
        }
    }
    float rz[8];
#pragma unroll
    for (int r = 0; r < 8; r++) rz[r] = d_rz[b * N + nb * 128 + tn * 8 + r];
#pragma unroll
    for (int s = 0; s < 8; s++) {
        int c = ch * 128 + tc * 8 + s;
        float bz = hb[c];
        __nv_bfloat16 hv[8];
#pragma unroll
        for (int r = 0; r < 8; r++) hv[r] = __float2bfloat16((acc[r][s] + bz) * rz[r]);
        size_t base = ((size_t)b * C + c) * N + nb * 128 + tn * 8;
        *(uint4*)&d_hTh[base] = *(uint4*)hv;
    }
}

// ---------------- pass 2 (merged ch): S-HMMA -> exp -> E -> O-HMMA (2 terms), out = O + x ----------------
// grid (32 ib, 8 b), 256 threads, dyn smem 180224
__global__ __launch_bounds__(256, 1) void k_out(const float* __restrict__ x, float* __restrict__ out) {
    extern __shared__ char sm[];
    const int SFH = 0, SFL = 10240, SGH = 20480, SGL = 30720;
    const int SEH = 40960, SEL = 75776, SHH = 110592;   // SHH: 256 rows * 272B = 69632
    uint32_t sb = smem_u32(sm);
    int tid = threadIdx.x, lane = tid & 31, w = tid >> 5;
    int ib = blockIdx.x, b = blockIdx.y;
    int wa = w & 3, wb = w >> 2;   // S phase: i-quarter / j-half

    for (int t = tid; t < 1024; t += 256) {
        int row = t >> 3, p = t & 7;
        uint4 v = ((const uint4*)d_fp)[(size_t)(b * N + ib * 128 + row) * 8 + p];
        *(uint4*)(sm + (p < 4 ? SFH + row * 80 + p * 16 : SFL + row * 80 + (p - 4) * 16)) = v;
    }
    float ao[2][16][4] = {};   // O phase: c rows = w*32 + mh*16 + .., i cols = n8*8 + ..

    for (int jb = 0; jb < 32; jb++) {
        __syncthreads();
        for (int t = tid; t < 1024; t += 256) {
            int row = t >> 3, p = t & 7;
            uint4 v = ((const uint4*)d_gp)[(size_t)(b * N + jb * 128 + row) * 8 + p];
            *(uint4*)(sm + (p < 4 ? SGH + row * 80 + p * 16 : SGL + row * 80 + (p - 4) * 16)) = v;
        }
        for (int t = tid; t < 4096; t += 256) {
            int row = t >> 4, u = t & 15;
            size_t src = (size_t)(b * C + row) * 512 + jb * 16 + u;
            *(uint4*)(sm + SHH + row * 272 + u * 16) = ((const uint4*)d_hTh)[src];
        }
        __syncthreads();

        // --- S tile: rows i = wa*32.., cols j = wb*64.. (3 terms) ---
        float as[2][8][4] = {};
#pragma unroll
        for (int term = 0; term < 3; term++) {
            int Ab = (term == 2) ? SFL : SFH;
            int Bb = (term == 1) ? SGL : SGH;
#pragma unroll
            for (int k16 = 0; k16 < 2; k16++) {
                uint32_t a0[4], a1[4];
                ldsm4(a0, sb + Ab + (wa * 32 +      (lane & 15)) * 80 + k16 * 32 + (lane >> 4) * 16);
                ldsm4(a1, sb + Ab + (wa * 32 + 16 + (lane & 15)) * 80 + k16 * 32 + (lane >> 4) * 16);
#pragma unroll
                for (int n8 = 0; n8 < 8; n8++) {
                    uint32_t bb[2];
                    ldsm2(bb, sb + Bb + (wb * 64 + n8 * 8 + (lane & 7)) * 80 + k16 * 32 + ((lane >> 3) & 1) * 16);
                    mma_bf16(as[0][n8], a0, bb);
                    mma_bf16(as[1][n8], a1, bb);
                }
            }
        }
        // --- exp + RN split -> sE (hi, lo) ---
#pragma unroll
        for (int mh = 0; mh < 2; mh++)
#pragma unroll
            for (int n8 = 0; n8 < 8; n8++) {
                int irow = wa * 32 + mh * 16 + (lane >> 2);
                int jcol = wb * 64 + n8 * 8 + 2 * (lane & 3);
#pragma unroll
                for (int hh = 0; hh < 2; hh++) {
                    float e0 = __expf(as[mh][n8][hh * 2 + 0]);
                    float e1 = __expf(as[mh][n8][hh * 2 + 1]);
                    __nv_bfloat16 b0 = __float2bfloat16(e0), b1 = __float2bfloat16(e1);
                    uint32_t hp = ((uint32_t)__bfloat16_as_ushort(b1) << 16) | __bfloat16_as_ushort(b0);
                    uint32_t lp = pack2(e0 - __bfloat162float(b0), e1 - __bfloat162float(b1));
                    *(uint32_t*)(sm + SEH + (irow + hh * 8) * 272 + jcol * 2) = hp;
                    *(uint32_t*)(sm + SEL + (irow + hh * 8) * 272 + jcol * 2) = lp;
                }
            }
        __syncthreads();

        // --- O tile: A = Hh rows c (w*32..), B = E rows i (all 128), k = j, 2 terms ---
#pragma unroll
        for (int k16 = 0; k16 < 8; k16++) {
            uint32_t a0[4], a1[4];
            ldsm4(a0, sb + SHH + (w * 32 +      (lane & 15)) * 272 + k16 * 32 + (lane >> 4) * 16);
            ldsm4(a1, sb + SHH + (w * 32 + 16 + (lane & 15)) * 272 + k16 * 32 + (lane >> 4) * 16);
#pragma unroll
            for (int n8 = 0; n8 < 16; n8++) {
                uint32_t bh[2], bl[2];
                ldsm2(bh, sb + SEH + (n8 * 8 + (lane & 7)) * 272 + k16 * 32 + ((lane >> 3) & 1) * 16);
                ldsm2(bl, sb + SEL + (n8 * 8 + (lane & 7)) * 272 + k16 * 32 + ((lane >> 3) & 1) * 16);
                mma_bf16(ao[0][n8], a0, bh);
                mma_bf16(ao[1][n8], a1, bh);
                mma_bf16(ao[0][n8], a0, bl);
                mma_bf16(ao[1][n8], a1, bl);
            }
        }
    }

    // epilogue: out[b][c][i] = O + x
#pragma unroll
    for (int mh = 0; mh < 2; mh++)
#pragma unroll
        for (int n8 = 0; n8 < 16; n8++) {
            int c = w * 32 + mh * 16 + (lane >> 2);
            int icol = ib * 128 + n8 * 8 + 2 * (lane & 3);
            size_t idx = (size_t)(b * C + c) * N + icol;
            float2 xv = *(const float2*)&x[idx];
            *(float2*)&out[idx] = make_float2(ao[mh][n8][0] + xv.x, ao[mh][n8][1] + xv.y);
            idx += (size_t)8 * N;
            xv = *(const float2*)&x[idx];
            *(float2*)&out[idx] = make_float2(ao[mh][n8][2] + xv.x, ao[mh][n8][3] + xv.y);
        }
}

// ---------------- launch ----------------
extern "C" void kernel_launch(void* const* d_in, const int* in_sizes, int n_in,
                              void* d_out, int out_size) {
    const float* x  = (const float*)d_in[0];
    const float* fw = (const float*)d_in[1];
    const float* fb = (const float*)d_in[2];
    const float* gw = (const float*)d_in[3];
    const float* gb = (const float*)d_in[4];
    const float* hw = (const float*)d_in[5];
    const float* hb = (const float*)d_in[6];
    float* out = (float*)d_out;

    const int SM_Z = 41984;
    const int SM_O = 180224;
    cudaFuncSetAttribute(k_zsum, cudaFuncAttributeMaxDynamicSharedMemorySize, SM_Z);
    cudaFuncSetAttribute(k_out,  cudaFuncAttributeMaxDynamicSharedMemorySize, SM_O);

    k_transpose_hw<<<256, 256>>>(hw);
    k_proj_fg<<<dim3(32, 8, 2), 256>>>(x, fw, fb, gw, gb);
    k_zsum<<<dim3(32, 8), 256, SM_Z>>>();
    k_proj_h<<<dim3(32, 8, 2), 256>>>(x, hb);
    k_out<<<dim3(32, 8), 256, SM_O>>>(x, out);
}

// round 8
// speedup vs baseline: 3.9005x; 1.2232x over previous
#include <cuda_runtime.h>
#include <cuda_fp16.h>
#include <cstdint>
#include <math.h>

#define Bn 8
#define C  256
#define N  4096

// ---------------- scratch ----------------
__device__ __half d_fp[Bn * N * 64];            // f packed fp16 [b][n][hi k0..31 | lo k0..31]
__device__ __half d_gp[Bn * N * 64];            // g packed
__device__ __half d_h [(size_t)Bn * C * N];     // H = h_w x + h_b, fp16 [b][c][j] (NOT Z-scaled)
__device__ float d_hwT[C * C];
__device__ float d_rz[Bn * N];                  // 1/Z_j

// ---------------- helpers ----------------
__device__ __forceinline__ uint32_t smem_u32(const void* p) {
    uint32_t a;
    asm("{ .reg .u64 t; cvta.to.shared.u64 t, %1; cvt.u32.u64 %0, t; }" : "=r"(a) : "l"(p));
    return a;
}
__device__ __forceinline__ void ldsm4(uint32_t* r, uint32_t a) {
    asm volatile("ldmatrix.sync.aligned.m8n8.x4.shared.b16 {%0,%1,%2,%3}, [%4];"
        : "=r"(r[0]), "=r"(r[1]), "=r"(r[2]), "=r"(r[3]) : "r"(a));
}
__device__ __forceinline__ void mma_f16(float* d, const uint32_t* a, const uint32_t* b) {
    asm volatile("mma.sync.aligned.m16n8k16.row.col.f32.f16.f16.f32 "
        "{%0,%1,%2,%3}, {%4,%5,%6,%7}, {%8,%9}, {%0,%1,%2,%3};"
        : "+f"(d[0]), "+f"(d[1]), "+f"(d[2]), "+f"(d[3])
        : "r"(a[0]), "r"(a[1]), "r"(a[2]), "r"(a[3]), "r"(b[0]), "r"(b[1]));
}
__device__ __forceinline__ void split2h(float v, __half& h, __half& l) {
    h = __float2half_rn(v);
    l = __float2half_rn(v - __half2float(h));
}

// ---------------- transpose h_w ----------------
__global__ void k_transpose_hw(const float* __restrict__ hw) {
    int idx = blockIdx.x * 256 + threadIdx.x;
    d_hwT[(idx & 255) * C + (idx >> 8)] = hw[idx];
}

// ---------------- f,g projections -> packed fp16 hi/lo ----------------
__global__ void k_proj_fg(const float* __restrict__ x,
                          const float* __restrict__ fw, const float* __restrict__ fb,
                          const float* __restrict__ gw, const float* __restrict__ gb) {
    __shared__ float xs[32][128];
    __shared__ float ws[32][32];
    int nb = blockIdx.x, b = blockIdx.y, which = blockIdx.z;
    const float* w    = which ? gw : fw;
    const float* bias = which ? gb : fb;
    __half* o = which ? d_gp : d_fp;
    int tid = threadIdx.x, oq = tid & 3, nq = tid >> 2;
    float acc[8][2] = {};
    for (int c0 = 0; c0 < 256; c0 += 32) {
        __syncthreads();
        for (int t = tid; t < 1024; t += 256)
            ((float4*)xs)[t] = ((const float4*)x)[((size_t)b * C + c0 + (t >> 5)) * 1024 + (size_t)nb * 32 + (t & 31)];
        for (int t = tid; t < 1024; t += 256)
            ws[t & 31][t >> 5] = w[(t >> 5) * C + c0 + (t & 31)];
        __syncthreads();
#pragma unroll
        for (int k = 0; k < 32; k++) {
            float x0 = xs[k][nq * 2], x1 = xs[k][nq * 2 + 1];
#pragma unroll
            for (int u = 0; u < 8; u++) {
                float wv = ws[k][oq * 8 + u];
                acc[u][0] += wv * x0;
                acc[u][1] += wv * x1;
            }
        }
    }
    int n0 = nb * 128 + nq * 2;
    size_t r0 = (size_t)(b * N + n0) * 64;
#pragma unroll
    for (int u = 0; u < 8; u++) {
        int oo = oq * 8 + u;
        float bz = bias[oo];
        __half h, l;
        split2h(acc[u][0] + bz, h, l);  o[r0 + oo] = h;       o[r0 + 32 + oo] = l;
        split2h(acc[u][1] + bz, h, l);  o[r0 + 64 + oo] = h;  o[r0 + 96 + oo] = l;
    }
}

// ---------------- pass 1: Z_j via HMMA (S^T tiles, 3-term fp16) ----------------
// grid (32 jb, 8 b), 256 threads, dyn smem 41984
__global__ __launch_bounds__(256, 1) void k_zsum() {
    extern __shared__ char sm[];
    const int SGH = 0, SGL = 10240, SFH = 20480, SFL = 30720, SZ = 40960;
    uint32_t sb = smem_u32(sm);
    int tid = threadIdx.x, lane = tid & 31, w = tid >> 5;
    int jb = blockIdx.x, b = blockIdx.y;
    int wj = w & 3, wi2 = w >> 2;

    for (int t = tid; t < 1024; t += 256) {
        int row = t >> 3, p = t & 7;
        uint4 v = ((const uint4*)d_gp)[(size_t)(b * N + jb * 128 + row) * 8 + p];
        *(uint4*)(sm + (p < 4 ? SGH + row * 80 + p * 16 : SGL + row * 80 + (p - 4) * 16)) = v;
    }
    float zacc[4] = {0.f, 0.f, 0.f, 0.f};

    for (int ibt = 0; ibt < 32; ibt++) {
        __syncthreads();
        for (int t = tid; t < 1024; t += 256) {
            int row = t >> 3, p = t & 7;
            uint4 v = ((const uint4*)d_fp)[(size_t)(b * N + ibt * 128 + row) * 8 + p];
            *(uint4*)(sm + (p < 4 ? SFH + row * 80 + p * 16 : SFL + row * 80 + (p - 4) * 16)) = v;
        }
        __syncthreads();
        float as[2][8][4] = {};
#pragma unroll
        for (int term = 0; term < 3; term++) {
            int Ab = (term == 2) ? SGL : SGH;   // A: gh, gh, gl
            int Bb = (term == 1) ? SFL : SFH;   // B: fh, fl, fh
#pragma unroll
            for (int k16 = 0; k16 < 2; k16++) {
                uint32_t a0[4], a1[4];
                ldsm4(a0, sb + Ab + (wj * 32 +      (lane & 15)) * 80 + k16 * 32 + (lane >> 4) * 16);
                ldsm4(a1, sb + Ab + (wj * 32 + 16 + (lane & 15)) * 80 + k16 * 32 + (lane >> 4) * 16);
#pragma unroll
                for (int p = 0; p < 4; p++) {
                    uint32_t bq[4];
                    ldsm4(bq, sb + Bb + (wi2 * 64 + p * 16 + ((lane >> 4) & 1) * 8 + (lane & 7)) * 80
                              + k16 * 32 + ((lane >> 3) & 1) * 16);
                    mma_f16(as[0][2 * p],     a0, bq);
                    mma_f16(as[1][2 * p],     a1, bq);
                    mma_f16(as[0][2 * p + 1], a0, bq + 2);
                    mma_f16(as[1][2 * p + 1], a1, bq + 2);
                }
            }
        }
#pragma unroll
        for (int mh = 0; mh < 2; mh++)
#pragma unroll
            for (int n8 = 0; n8 < 8; n8++) {
                zacc[mh * 2 + 0] += __expf(as[mh][n8][0]) + __expf(as[mh][n8][1]);
                zacc[mh * 2 + 1] += __expf(as[mh][n8][2]) + __expf(as[mh][n8][3]);
            }
    }
#pragma unroll
    for (int m = 0; m < 4; m++) {
        float v = zacc[m];
        v += __shfl_xor_sync(0xffffffffu, v, 1);
        v += __shfl_xor_sync(0xffffffffu, v, 2);
        if ((lane & 3) == 0) {
            int jloc = wj * 32 + (m >> 1) * 16 + (m & 1) * 8 + (lane >> 2);
            *(float*)(sm + SZ + (wi2 * 128 + jloc) * 4) = v;
        }
    }
    __syncthreads();
    if (tid < 128) {
        float z = *(float*)(sm + SZ + tid * 4) + *(float*)(sm + SZ + (128 + tid) * 4);
        d_rz[b * N + jb * 128 + tid] = 1.f / z;
    }
}

// ---------------- h projection -> H fp16 [b][c][j] (unnormalized) ----------------
__global__ void k_proj_h(const float* __restrict__ x, const float* __restrict__ hb) {
    __shared__ float xs[32][128];
    __shared__ float ws[32][128];
    int nb = blockIdx.x, b = blockIdx.y, ch = blockIdx.z;
    int tid = threadIdx.x, tn = tid & 15, tc = tid >> 4;
    float acc[8][8] = {};
    for (int c0 = 0; c0 < 256; c0 += 32) {
        __syncthreads();
        for (int t = tid; t < 1024; t += 256) {
            ((float4*)xs)[t] = ((const float4*)x)[((size_t)b * C + c0 + (t >> 5)) * 1024 + (size_t)nb * 32 + (t & 31)];
            ((float4*)ws)[t] = ((const float4*)d_hwT)[(size_t)(c0 + (t >> 5)) * 64 + ch * 32 + (t & 31)];
        }
        __syncthreads();
#pragma unroll 8
        for (int k = 0; k < 32; k++) {
            float a[8], wv[8];
            *(float4*)(a)      = *(float4*)&xs[k][tn * 8];
            *(float4*)(a + 4)  = *(float4*)&xs[k][tn * 8 + 4];
            *(float4*)(wv)     = *(float4*)&ws[k][tc * 8];
            *(float4*)(wv + 4) = *(float4*)&ws[k][tc * 8 + 4];
#pragma unroll
            for (int r = 0; r < 8; r++)
#pragma unroll
                for (int s = 0; s < 8; s++) acc[r][s] += a[r] * wv[s];
        }
    }
#pragma unroll
    for (int s = 0; s < 8; s++) {
        int c = ch * 128 + tc * 8 + s;
        float bz = hb[c];
        __half hv[8];
#pragma unroll
        for (int r = 0; r < 8; r++) hv[r] = __float2half_rn(acc[r][s] + bz);
        size_t base = ((size_t)b * C + c) * N + nb * 128 + tn * 8;
        *(uint4*)&d_h[base] = *(uint4*)hv;
    }
}

// ---------------- pass 2: S (3-term) -> exp*rz -> E fp16 -> O (1-term), out = O + x ----------------
// grid (32 ib, 8 b), 256 threads, dyn smem 145920
__global__ __launch_bounds__(256, 1) void k_out(const float* __restrict__ x, float* __restrict__ out) {
    extern __shared__ char sm[];
    const int SFH = 0, SFL = 10240, SGH = 20480, SGL = 30720;
    const int SE = 40960, SH = 75776, SR = 145408;   // SE 128*272, SH 256*272
    uint32_t sb = smem_u32(sm);
    int tid = threadIdx.x, lane = tid & 31, w = tid >> 5;
    int ib = blockIdx.x, b = blockIdx.y;
    int wa = w & 3, wb = w >> 2;   // S phase: i-quarter / j-half

    for (int t = tid; t < 1024; t += 256) {
        int row = t >> 3, p = t & 7;
        uint4 v = ((const uint4*)d_fp)[(size_t)(b * N + ib * 128 + row) * 8 + p];
        *(uint4*)(sm + (p < 4 ? SFH + row * 80 + p * 16 : SFL + row * 80 + (p - 4) * 16)) = v;
    }
    float ao[2][16][4] = {};   // O phase: c rows = w*32.., i cols = n8*8..

    for (int jb = 0; jb < 32; jb++) {
        __syncthreads();
        for (int t = tid; t < 1024; t += 256) {
            int row = t >> 3, p = t & 7;
            uint4 v = ((const uint4*)d_gp)[(size_t)(b * N + jb * 128 + row) * 8 + p];
            *(uint4*)(sm + (p < 4 ? SGH + row * 80 + p * 16 : SGL + row * 80 + (p - 4) * 16)) = v;
        }
        for (int t = tid; t < 4096; t += 256) {
            int row = t >> 4, u = t & 15;
            size_t src = (size_t)(b * C + row) * (size_t)N + jb * 128 + u * 8;   // half elements
            *(uint4*)(sm + SH + row * 272 + u * 16) = *(const uint4*)&d_h[src];
        }
        if (tid < 128) *(float*)(sm + SR + tid * 4) = d_rz[b * N + jb * 128 + tid];
        __syncthreads();

        // --- S tile: rows i = wa*32.., cols j = wb*64.. (3 terms) ---
        float as[2][8][4] = {};
#pragma unroll
        for (int term = 0; term < 3; term++) {
            int Ab = (term == 2) ? SFL : SFH;
            int Bb = (term == 1) ? SGL : SGH;
#pragma unroll
            for (int k16 = 0; k16 < 2; k16++) {
                uint32_t a0[4], a1[4];
                ldsm4(a0, sb + Ab + (wa * 32 +      (lane & 15)) * 80 + k16 * 32 + (lane >> 4) * 16);
                ldsm4(a1, sb + Ab + (wa * 32 + 16 + (lane & 15)) * 80 + k16 * 32 + (lane >> 4) * 16);
#pragma unroll
                for (int p = 0; p < 4; p++) {
                    uint32_t bq[4];
                    ldsm4(bq, sb + Bb + (wb * 64 + p * 16 + ((lane >> 4) & 1) * 8 + (lane & 7)) * 80
                              + k16 * 32 + ((lane >> 3) & 1) * 16);
                    mma_f16(as[0][2 * p],     a0, bq);
                    mma_f16(as[1][2 * p],     a1, bq);
                    mma_f16(as[0][2 * p + 1], a0, bq + 2);
                    mma_f16(as[1][2 * p + 1], a1, bq + 2);
                }
            }
        }
        // --- E = exp(S) * rz_j -> fp16 ---
#pragma unroll
        for (int mh = 0; mh < 2; mh++)
#pragma unroll
            for (int n8 = 0; n8 < 8; n8++) {
                int irow = wa * 32 + mh * 16 + (lane >> 2);
                int jcol = wb * 64 + n8 * 8 + 2 * (lane & 3);
                float2 rzv = *(float2*)(sm + SR + jcol * 4);
#pragma unroll
                for (int hh = 0; hh < 2; hh++) {
                    float e0 = __expf(as[mh][n8][hh * 2 + 0]) * rzv.x;
                    float e1 = __expf(as[mh][n8][hh * 2 + 1]) * rzv.y;
                    __half2 hp = __floats2half2_rn(e0, e1);
                    *(uint32_t*)(sm + SE + (irow + hh * 8) * 272 + jcol * 2) = *(uint32_t*)&hp;
                }
            }
        __syncthreads();

        // --- O tile: A = H rows c (w*32..), B = E rows i (all 128), k = j, 1 term ---
#pragma unroll
        for (int k16 = 0; k16 < 8; k16++) {
            uint32_t a0[4], a1[4];
            ldsm4(a0, sb + SH + (w * 32 +      (lane & 15)) * 272 + k16 * 32 + (lane >> 4) * 16);
            ldsm4(a1, sb + SH + (w * 32 + 16 + (lane & 15)) * 272 + k16 * 32 + (lane >> 4) * 16);
#pragma unroll
            for (int p = 0; p < 8; p++) {
                uint32_t bq[4];
                ldsm4(bq, sb + SE + (p * 16 + ((lane >> 4) & 1) * 8 + (lane & 7)) * 272
                          + k16 * 32 + ((lane >> 3) & 1) * 16);
                mma_f16(ao[0][2 * p],     a0, bq);
                mma_f16(ao[1][2 * p],     a1, bq);
                mma_f16(ao[0][2 * p + 1], a0, bq + 2);
                mma_f16(ao[1][2 * p + 1], a1, bq + 2);
            }
        }
    }

    // epilogue: out[b][c][i] = O + x
#pragma unroll
    for (int mh = 0; mh < 2; mh++)
#pragma unroll
        for (int n8 = 0; n8 < 16; n8++) {
            int c = w * 32 + mh * 16 + (lane >> 2);
            int icol = ib * 128 + n8 * 8 + 2 * (lane & 3);
            size_t idx = (size_t)(b * C + c) * N + icol;
            float2 xv = *(const float2*)&x[idx];
            *(float2*)&out[idx] = make_float2(ao[mh][n8][0] + xv.x, ao[mh][n8][1] + xv.y);
            idx += (size_t)8 * N;
            xv = *(const float2*)&x[idx];
            *(float2*)&out[idx] = make_float2(ao[mh][n8][2] + xv.x, ao[mh][n8][3] + xv.y);
        }
}

// ---------------- launch ----------------
extern "C" void kernel_launch(void* const* d_in, const int* in_sizes, int n_in,
                              void* d_out, int out_size) {
    const float* x  = (const float*)d_in[0];
    const float* fw = (const float*)d_in[1];
    const float* fb = (const float*)d_in[2];
    const float* gw = (const float*)d_in[3];
    const float* gb = (const float*)d_in[4];
    const float* hw = (const float*)d_in[5];
    const float* hb = (const float*)d_in[6];
    float* out = (float*)d_out;

    const int SM_Z = 41984;
    const int SM_O = 145920;
    cudaFuncSetAttribute(k_zsum, cudaFuncAttributeMaxDynamicSharedMemorySize, SM_Z);
    cudaFuncSetAttribute(k_out,  cudaFuncAttributeMaxDynamicSharedMemorySize, SM_O);

    k_transpose_hw<<<256, 256>>>(hw);
    k_proj_fg<<<dim3(32, 8, 2), 256>>>(x, fw, fb, gw, gb);
    k_zsum<<<dim3(32, 8), 256, SM_Z>>>();
    k_proj_h<<<dim3(32, 8, 2), 256>>>(x, hb);
    k_out<<<dim3(32, 8), 256, SM_O>>>(x, out);
}

// round 9
// speedup vs baseline: 4.9333x; 1.2648x over previous
#include <cuda_runtime.h>
#include <cuda_fp16.h>
#include <cstdint>
#include <math.h>

#define Bn 8
#define C  256
#define N  4096

// ---------------- scratch ----------------
__device__ __half d_fp[Bn * N * 64];            // f packed fp16 [b][n][hi k0..31 | lo k0..31]
__device__ __half d_gp[Bn * N * 64];            // g packed
__device__ __half d_h [(size_t)Bn * C * N];     // H = h_w x + h_b, fp16 [b][c][j] (NOT Z-scaled)
__device__ float d_rz[Bn * N];                  // 1/Z_j

// ---------------- helpers ----------------
__device__ __forceinline__ uint32_t smem_u32(const void* p) {
    uint32_t a;
    asm("{ .reg .u64 t; cvta.to.shared.u64 t, %1; cvt.u32.u64 %0, t; }" : "=r"(a) : "l"(p));
    return a;
}
__device__ __forceinline__ void ldsm4(uint32_t* r, uint32_t a) {
    asm volatile("ldmatrix.sync.aligned.m8n8.x4.shared.b16 {%0,%1,%2,%3}, [%4];"
        : "=r"(r[0]), "=r"(r[1]), "=r"(r[2]), "=r"(r[3]) : "r"(a));
}
__device__ __forceinline__ void mma_f16(float* d, const uint32_t* a, const uint32_t* b) {
    asm volatile("mma.sync.aligned.m16n8k16.row.col.f32.f16.f16.f32 "
        "{%0,%1,%2,%3}, {%4,%5,%6,%7}, {%8,%9}, {%0,%1,%2,%3};"
        : "+f"(d[0]), "+f"(d[1]), "+f"(d[2]), "+f"(d[3])
        : "r"(a[0]), "r"(a[1]), "r"(a[2]), "r"(a[3]), "r"(b[0]), "r"(b[1]));
}
__device__ __forceinline__ void split2h(float v, __half& h, __half& l) {
    h = __float2half_rn(v);
    l = __float2half_rn(v - __half2float(h));
}
__device__ __forceinline__ void cp16(uint32_t dst, const void* src) {
    asm volatile("cp.async.cg.shared.global [%0], [%1], 16;" :: "r"(dst), "l"(src));
}
#define CP_COMMIT() asm volatile("cp.async.commit_group;" ::: "memory")
#define CP_WAIT1()  asm volatile("cp.async.wait_group 1;" ::: "memory")

// ---------------- merged projections: f,g packed + H fp16, via 3-term fp16 HMMA ----------------
// grid (32 nb, 8 b), 512 threads, dyn smem 71680
__global__ __launch_bounds__(512, 1) void k_proj(
    const float* __restrict__ x,
    const float* __restrict__ fw, const float* __restrict__ fb,
    const float* __restrict__ gw, const float* __restrict__ gb,
    const float* __restrict__ hw, const float* __restrict__ hb) {
    extern __shared__ char sm[];
    const int WH = 0, WL = 25600, XH = 51200, XL = 61440;  // W 320x(32+pad), X 128x(32+pad)
    uint32_t sb = smem_u32(sm);
    int tid = threadIdx.x, lane = tid & 31, w = tid >> 5;
    int nb = blockIdx.x, b = blockIdx.y;
    int wm = w & 3, wn = w >> 2;   // m quarter (80 rows), n quarter (32 cols)
    float ap[5][4][4] = {};

    for (int c0 = 0; c0 < 256; c0 += 32) {
        __syncthreads();
        for (int idx = tid; idx < 10240; idx += 512) {
            int row = idx >> 5, cc = idx & 31;
            const float* wp = row < 32 ? fw + row * 256
                             : row < 64 ? gw + (row - 32) * 256
                                        : hw + (row - 64) * 256;
            __half h, l;
            split2h(wp[c0 + cc], h, l);
            *(__half*)(sm + WH + row * 80 + cc * 2) = h;
            *(__half*)(sm + WL + row * 80 + cc * 2) = l;
        }
        for (int idx = tid; idx < 4096; idx += 512) {
            int cc = idx >> 7, n = idx & 127;
            __half h, l;
            split2h(x[((size_t)b * 256 + c0 + cc) * 4096 + nb * 128 + n], h, l);
            *(__half*)(sm + XH + n * 80 + cc * 2) = h;
            *(__half*)(sm + XL + n * 80 + cc * 2) = l;
        }
        __syncthreads();
#pragma unroll
        for (int term = 0; term < 3; term++) {
            int Ab = term == 2 ? WL : WH;
            int Bb = term == 1 ? XL : XH;
#pragma unroll
            for (int k16 = 0; k16 < 2; k16++) {
                uint32_t af[5][4];
#pragma unroll
                for (int mi = 0; mi < 5; mi++)
                    ldsm4(af[mi], sb + Ab + (wm * 80 + mi * 16 + (lane & 15)) * 80 + k16 * 32 + (lane >> 4) * 16);
#pragma unroll
                for (int p = 0; p < 2; p++) {
                    uint32_t bq[4];
                    ldsm4(bq, sb + Bb + (wn * 32 + p * 16 + ((lane >> 4) & 1) * 8 + (lane & 7)) * 80
                              + k16 * 32 + ((lane >> 3) & 1) * 16);
#pragma unroll
                    for (int mi = 0; mi < 5; mi++) {
                        mma_f16(ap[mi][2 * p],     af[mi], bq);
                        mma_f16(ap[mi][2 * p + 1], af[mi], bq + 2);
                    }
                }
            }
        }
    }
    // epilogue: rows 0-31 -> f packed, 32-63 -> g packed, 64-319 -> H
#pragma unroll
    for (int mi = 0; mi < 5; mi++)
#pragma unroll
        for (int p = 0; p < 4; p++)
#pragma unroll
            for (int hf = 0; hf < 2; hf++) {
                int orow = wm * 80 + mi * 16 + hf * 8 + (lane >> 2);
                int n = nb * 128 + wn * 32 + p * 8 + 2 * (lane & 3);
                float v0 = ap[mi][p][hf * 2 + 0];
                float v1 = ap[mi][p][hf * 2 + 1];
                if (orow < 64) {
                    __half* o = orow < 32 ? d_fp : d_gp;
                    int oo = orow & 31;
                    float bz = orow < 32 ? fb[oo] : gb[oo];
                    __half h, l;
                    split2h(v0 + bz, h, l);
                    o[((size_t)b * N + n) * 64 + oo] = h;
                    o[((size_t)b * N + n) * 64 + 32 + oo] = l;
                    split2h(v1 + bz, h, l);
                    o[((size_t)b * N + n + 1) * 64 + oo] = h;
                    o[((size_t)b * N + n + 1) * 64 + 32 + oo] = l;
                } else {
                    int c = orow - 64;
                    float bz = hb[c];
                    __half2 hv = __floats2half2_rn(v0 + bz, v1 + bz);
                    *(__half2*)&d_h[((size_t)b * C + c) * N + n] = hv;
                }
            }
}

// ---------------- pass 1: Z_j via HMMA, 2-term (gh·fh + gh·fl), cp.async pipelined ----------------
// grid (32 jb, 8 b), 256 threads, dyn smem 52224
__global__ __launch_bounds__(256, 1) void k_zsum() {
    extern __shared__ char sm[];
    const int SG = 0;                                  // gh only, 128*80
    const int SFH[2] = {10240, 30720}, SFL[2] = {20480, 40960};
    const int SZ = 51200;
    uint32_t sb = smem_u32(sm);
    int tid = threadIdx.x, lane = tid & 31, w = tid >> 5;
    int jb = blockIdx.x, b = blockIdx.y;
    int wj = w & 3, wi2 = w >> 2;

    for (int t = tid; t < 512; t += 256) {   // gh: p<4 halves only
        int row = t >> 2, p = t & 3;
        *(uint4*)(sm + SG + row * 80 + p * 16) =
            ((const uint4*)d_gp)[(size_t)(b * N + jb * 128 + row) * 8 + p];
    }
    // prefetch f tile 0
    for (int t = tid; t < 1024; t += 256) {
        int row = t >> 3, p = t & 7;
        const char* src = (const char*)d_fp + ((size_t)(b * N + row) * 8 + p) * 16;
        cp16(sb + (p < 4 ? SFH[0] + row * 80 + p * 16 : SFL[0] + row * 80 + (p - 4) * 16), src);
    }
    CP_COMMIT();

    float zacc[4] = {0.f, 0.f, 0.f, 0.f};
    for (int ibt = 0; ibt < 32; ibt++) {
        int cur = ibt & 1;
        __syncthreads();
        if (ibt < 31) {
            int nxt = 1 - cur;
            for (int t = tid; t < 1024; t += 256) {
                int row = t >> 3, p = t & 7;
                const char* src = (const char*)d_fp + ((size_t)(b * N + (ibt + 1) * 128 + row) * 8 + p) * 16;
                cp16(sb + (p < 4 ? SFH[nxt] + row * 80 + p * 16 : SFL[nxt] + row * 80 + (p - 4) * 16), src);
            }
        }
        CP_COMMIT();
        CP_WAIT1();
        __syncthreads();

        float as[2][8][4] = {};
#pragma unroll
        for (int k16 = 0; k16 < 2; k16++) {
            uint32_t a0[4], a1[4];
            ldsm4(a0, sb + SG + (wj * 32 +      (lane & 15)) * 80 + k16 * 32 + (lane >> 4) * 16);
            ldsm4(a1, sb + SG + (wj * 32 + 16 + (lane & 15)) * 80 + k16 * 32 + (lane >> 4) * 16);
#pragma unroll
            for (int term = 0; term < 2; term++) {
                int Bb = term ? SFL[cur] : SFH[cur];
#pragma unroll
                for (int p = 0; p < 4; p++) {
                    uint32_t bq[4];
                    ldsm4(bq, sb + Bb + (wi2 * 64 + p * 16 + ((lane >> 4) & 1) * 8 + (lane & 7)) * 80
                              + k16 * 32 + ((lane >> 3) & 1) * 16);
                    mma_f16(as[0][2 * p],     a0, bq);
                    mma_f16(as[1][2 * p],     a1, bq);
                    mma_f16(as[0][2 * p + 1], a0, bq + 2);
                    mma_f16(as[1][2 * p + 1], a1, bq + 2);
                }
            }
        }
#pragma unroll
        for (int mh = 0; mh < 2; mh++)
#pragma unroll
            for (int n8 = 0; n8 < 8; n8++) {
                zacc[mh * 2 + 0] += __expf(as[mh][n8][0]) + __expf(as[mh][n8][1]);
                zacc[mh * 2 + 1] += __expf(as[mh][n8][2]) + __expf(as[mh][n8][3]);
            }
    }
#pragma unroll
    for (int m = 0; m < 4; m++) {
        float v = zacc[m];
        v += __shfl_xor_sync(0xffffffffu, v, 1);
        v += __shfl_xor_sync(0xffffffffu, v, 2);
        if ((lane & 3) == 0) {
            int jloc = wj * 32 + (m >> 1) * 16 + (m & 1) * 8 + (lane >> 2);
            *(float*)(sm + SZ + (wi2 * 128 + jloc) * 4) = v;
        }
    }
    __syncthreads();
    if (tid < 128) {
        float z = *(float*)(sm + SZ + tid * 4) + *(float*)(sm + SZ + (128 + tid) * 4);
        d_rz[b * N + jb * 128 + tid] = 1.f / z;
    }
}

// ---------------- pass 2: S (3-term) -> exp*rz -> E fp16 -> O (1-term), H double-buffered ----------------
// grid (32 ib, 8 b), 256 threads, dyn smem 215552
__global__ __launch_bounds__(256, 1) void k_out(const float* __restrict__ x, float* __restrict__ out) {
    extern __shared__ char sm[];
    const int SFH = 0, SFL = 10240, SGH = 20480, SGL = 30720;
    const int SE = 40960;                       // 128*272
    const int SHB[2] = {75776, 145408};         // 2 x 256*272
    const int SR = 215040;
    uint32_t sb = smem_u32(sm);
    int tid = threadIdx.x, lane = tid & 31, w = tid >> 5;
    int ib = blockIdx.x, b = blockIdx.y;
    int wa = w & 3, wb = w >> 2;   // S phase: i-quarter / j-half

    for (int t = tid; t < 1024; t += 256) {
        int row = t >> 3, p = t & 7;
        uint4 v = ((const uint4*)d_fp)[(size_t)(b * N + ib * 128 + row) * 8 + p];
        *(uint4*)(sm + (p < 4 ? SFH + row * 80 + p * 16 : SFL + row * 80 + (p - 4) * 16)) = v;
    }
    // prefetch H tile 0
    for (int t = tid; t < 4096; t += 256) {
        int row = t >> 4, u = t & 15;
        const char* src = (const char*)d_h + ((size_t)(b * C + row) * N + u * 8) * 2;
        cp16(sb + SHB[0] + row * 272 + u * 16, src);
    }
    CP_COMMIT();

    float ao[2][16][4] = {};
    for (int jb = 0; jb < 32; jb++) {
        int cur = jb & 1;
        __syncthreads();
        if (jb < 31) {
            int nxt = 1 - cur;
            for (int t = tid; t < 4096; t += 256) {
                int row = t >> 4, u = t & 15;
                const char* src = (const char*)d_h + ((size_t)(b * C + row) * N + (jb + 1) * 128 + u * 8) * 2;
                cp16(sb + SHB[nxt] + row * 272 + u * 16, src);
            }
        }
        CP_COMMIT();
        for (int t = tid; t < 1024; t += 256) {
            int row = t >> 3, p = t & 7;
            uint4 v = ((const uint4*)d_gp)[(size_t)(b * N + jb * 128 + row) * 8 + p];
            *(uint4*)(sm + (p < 4 ? SGH + row * 80 + p * 16 : SGL + row * 80 + (p - 4) * 16)) = v;
        }
        if (tid < 128) *(float*)(sm + SR + tid * 4) = d_rz[b * N + jb * 128 + tid];
        CP_WAIT1();
        __syncthreads();

        // --- S tile (3 terms, fh A-frags shared between gh/gl) ---
        float as[2][8][4] = {};
#pragma unroll
        for (int k16 = 0; k16 < 2; k16++) {
            uint32_t a0[4], a1[4];
            ldsm4(a0, sb + SFH + (wa * 32 +      (lane & 15)) * 80 + k16 * 32 + (lane >> 4) * 16);
            ldsm4(a1, sb + SFH + (wa * 32 + 16 + (lane & 15)) * 80 + k16 * 32 + (lane >> 4) * 16);
#pragma unroll
            for (int term = 0; term < 2; term++) {
                int Bb = term ? SGL : SGH;
#pragma unroll
                for (int p = 0; p < 4; p++) {
                    uint32_t bq[4];
                    ldsm4(bq, sb + Bb + (wb * 64 + p * 16 + ((lane >> 4) & 1) * 8 + (lane & 7)) * 80
                              + k16 * 32 + ((lane >> 3) & 1) * 16);
                    mma_f16(as[0][2 * p],     a0, bq);
                    mma_f16(as[1][2 * p],     a1, bq);
                    mma_f16(as[0][2 * p + 1], a0, bq + 2);
                    mma_f16(as[1][2 * p + 1], a1, bq + 2);
                }
            }
            ldsm4(a0, sb + SFL + (wa * 32 +      (lane & 15)) * 80 + k16 * 32 + (lane >> 4) * 16);
            ldsm4(a1, sb + SFL + (wa * 32 + 16 + (lane & 15)) * 80 + k16 * 32 + (lane >> 4) * 16);
#pragma unroll
            for (int p = 0; p < 4; p++) {
                uint32_t bq[4];
                ldsm4(bq, sb + SGH + (wb * 64 + p * 16 + ((lane >> 4) & 1) * 8 + (lane & 7)) * 80
                          + k16 * 32 + ((lane >> 3) & 1) * 16);
                mma_f16(as[0][2 * p],     a0, bq);
                mma_f16(as[1][2 * p],     a1, bq);
                mma_f16(as[0][2 * p + 1], a0, bq + 2);
                mma_f16(as[1][2 * p + 1], a1, bq + 2);
            }
        }
        // --- E = exp(S) * rz_j -> fp16 ---
#pragma unroll
        for (int mh = 0; mh < 2; mh++)
#pragma unroll
            for (int n8 = 0; n8 < 8; n8++) {
                int irow = wa * 32 + mh * 16 + (lane >> 2);
                int jcol = wb * 64 + n8 * 8 + 2 * (lane & 3);
                float2 rzv = *(float2*)(sm + SR + jcol * 4);
#pragma unroll
                for (int hh = 0; hh < 2; hh++) {
                    float e0 = __expf(as[mh][n8][hh * 2 + 0]) * rzv.x;
                    float e1 = __expf(as[mh][n8][hh * 2 + 1]) * rzv.y;
                    __half2 hp = __floats2half2_rn(e0, e1);
                    *(uint32_t*)(sm + SE + (irow + hh * 8) * 272 + jcol * 2) = *(uint32_t*)&hp;
                }
            }
        __syncthreads();

        // --- O tile: A = H rows c (w*32..), B = E rows i, k = j ---
        int SH = SHB[cur];
#pragma unroll
        for (int k16 = 0; k16 < 8; k16++) {
            uint32_t a0[4], a1[4];
            ldsm4(a0, sb + SH + (w * 32 +      (lane & 15)) * 272 + k16 * 32 + (lane >> 4) * 16);
            ldsm4(a1, sb + SH + (w * 32 + 16 + (lane & 15)) * 272 + k16 * 32 + (lane >> 4) * 16);
#pragma unroll
            for (int p = 0; p < 8; p++) {
                uint32_t bq[4];
                ldsm4(bq, sb + SE + (p * 16 + ((lane >> 4) & 1) * 8 + (lane & 7)) * 272
                          + k16 * 32 + ((lane >> 3) & 1) * 16);
                mma_f16(ao[0][2 * p],     a0, bq);
                mma_f16(ao[1][2 * p],     a1, bq);
                mma_f16(ao[0][2 * p + 1], a0, bq + 2);
                mma_f16(ao[1][2 * p + 1], a1, bq + 2);
            }
        }
    }

    // epilogue: out[b][c][i] = O + x
#pragma unroll
    for (int mh = 0; mh < 2; mh++)
#pragma unroll
        for (int n8 = 0; n8 < 16; n8++) {
            int c = w * 32 + mh * 16 + (lane >> 2);
            int icol = ib * 128 + n8 * 8 + 2 * (lane & 3);
            size_t idx = (size_t)(b * C + c) * N + icol;
            float2 xv = *(const float2*)&x[idx];
            *(float2*)&out[idx] = make_float2(ao[mh][n8][0] + xv.x, ao[mh][n8][1] + xv.y);
            idx += (size_t)8 * N;
            xv = *(const float2*)&x[idx];
            *(float2*)&out[idx] = make_float2(ao[mh][n8][2] + xv.x, ao[mh][n8][3] + xv.y);
        }
}

// ---------------- launch ----------------
extern "C" void kernel_launch(void* const* d_in, const int* in_sizes, int n_in,
                              void* d_out, int out_size) {
    const float* x  = (const float*)d_in[0];
    const float* fw = (const float*)d_in[1];
    const float* fb = (const float*)d_in[2];
    const float* gw = (const float*)d_in[3];
    const float* gb = (const float*)d_in[4];
    const float* hw = (const float*)d_in[5];
    const float* hb = (const float*)d_in[6];
    float* out = (float*)d_out;

    const int SM_P = 71680;
    const int SM_Z = 52224;
    const int SM_O = 215552;
    cudaFuncSetAttribute(k_proj, cudaFuncAttributeMaxDynamicSharedMemorySize, SM_P);
    cudaFuncSetAttribute(k_zsum, cudaFuncAttributeMaxDynamicSharedMemorySize, SM_Z);
    cudaFuncSetAttribute(k_out,  cudaFuncAttributeMaxDynamicSharedMemorySize, SM_O);

    k_proj<<<dim3(32, 8), 512, SM_P>>>(x, fw, fb, gw, gb, hw, hb);
    k_zsum<<<dim3(32, 8), 256, SM_Z>>>();
    k_out<<<dim3(32, 8), 256, SM_O>>>(x, out);
}

// round 10
// speedup vs baseline: 5.5452x; 1.1240x over previous
#include <cuda_runtime.h>
#include <cuda_fp16.h>
#include <cstdint>
#include <math.h>

#define Bn 8
#define C  256
#define N  4096

// ---------------- scratch ----------------
__device__ __half d_fp[Bn * N * 64];            // f packed fp16 [b][n][hi k0..31 | lo k0..31]
__device__ __half d_gp[Bn * N * 64];            // g packed
__device__ __half d_h [(size_t)Bn * C * N];     // H = h_w x + h_b, fp16 [b][c][j] (NOT Z-scaled)
__device__ __half d_wh[320 * 256];              // W = [fw;gw;hw] split hi
__device__ __half d_wl[320 * 256];              // W split lo
__device__ float d_rz[Bn * N];                  // 1/Z_j

// ---------------- helpers ----------------
__device__ __forceinline__ uint32_t smem_u32(const void* p) {
    uint32_t a;
    asm("{ .reg .u64 t; cvta.to.shared.u64 t, %1; cvt.u32.u64 %0, t; }" : "=r"(a) : "l"(p));
    return a;
}
__device__ __forceinline__ void ldsm4(uint32_t* r, uint32_t a) {
    asm volatile("ldmatrix.sync.aligned.m8n8.x4.shared.b16 {%0,%1,%2,%3}, [%4];"
        : "=r"(r[0]), "=r"(r[1]), "=r"(r[2]), "=r"(r[3]) : "r"(a));
}
__device__ __forceinline__ void mma_f16(float* d, const uint32_t* a, const uint32_t* b) {
    asm volatile("mma.sync.aligned.m16n8k16.row.col.f32.f16.f16.f32 "
        "{%0,%1,%2,%3}, {%4,%5,%6,%7}, {%8,%9}, {%0,%1,%2,%3};"
        : "+f"(d[0]), "+f"(d[1]), "+f"(d[2]), "+f"(d[3])
        : "r"(a[0]), "r"(a[1]), "r"(a[2]), "r"(a[3]), "r"(b[0]), "r"(b[1]));
}
__device__ __forceinline__ void split2h(float v, __half& h, __half& l) {
    h = __float2half_rn(v);
    l = __float2half_rn(v - __half2float(h));
}
__device__ __forceinline__ void cp16(uint32_t dst, const void* src) {
    asm volatile("cp.async.cg.shared.global [%0], [%1], 16;" :: "r"(dst), "l"(src));
}
#define CP_COMMIT() asm volatile("cp.async.commit_group;" ::: "memory")
#define CP_WAIT0()  asm volatile("cp.async.wait_group 0;" ::: "memory")
#define CP_WAIT1()  asm volatile("cp.async.wait_group 1;" ::: "memory")

// ---------------- W pre-split: [fw;gw;hw] -> packed fp16 hi/lo ----------------
__global__ __launch_bounds__(512) void k_prep(const float* __restrict__ fw,
                                              const float* __restrict__ gw,
                                              const float* __restrict__ hw) {
    int idx = blockIdx.x * 512 + threadIdx.x;   // 81920
    int row = idx >> 8, cc = idx & 255;
    const float* wp = row < 32 ? fw + row * 256
                     : row < 64 ? gw + (row - 32) * 256
                                : hw + (row - 64) * 256;
    __half h, l;
    split2h(wp[cc], h, l);
    d_wh[idx] = h;
    d_wl[idx] = l;
}

// ---------------- merged projections via 3-term fp16 HMMA, W tiles via cp.async ----------------
// grid (32 nb, 8 b), 512 threads, dyn smem 71680
__global__ __launch_bounds__(512, 1) void k_proj(
    const float* __restrict__ x,
    const float* __restrict__ fb, const float* __restrict__ gb, const float* __restrict__ hb) {
    extern __shared__ char sm[];
    const int WH = 0, WL = 25600, XH = 51200, XL = 61440;  // W 320x(32+pad), X 128x(32+pad)
    uint32_t sb = smem_u32(sm);
    int tid = threadIdx.x, lane = tid & 31, w = tid >> 5;
    int nb = blockIdx.x, b = blockIdx.y;
    int wm = w & 3, wn = w >> 2;   // m quarter (80 rows), n quarter (32 cols)
    float ap[5][4][4] = {};

    for (int c0 = 0; c0 < 256; c0 += 32) {
        __syncthreads();
        // W tiles via cp.async (overlaps with x split below)
        for (int t = tid; t < 1280; t += 512) {
            int row = t >> 2, p = t & 3;
            cp16(sb + WH + row * 80 + p * 16, (const char*)d_wh + (row * 256 + c0 + p * 8) * 2);
            cp16(sb + WL + row * 80 + p * 16, (const char*)d_wl + (row * 256 + c0 + p * 8) * 2);
        }
        CP_COMMIT();
        // x split (ALU work hides the async copies)
        for (int idx = tid; idx < 4096; idx += 512) {
            int cc = idx >> 7, n = idx & 127;
            __half h, l;
            split2h(x[((size_t)b * 256 + c0 + cc) * 4096 + nb * 128 + n], h, l);
            *(__half*)(sm + XH + n * 80 + cc * 2) = h;
            *(__half*)(sm + XL + n * 80 + cc * 2) = l;
        }
        CP_WAIT0();
        __syncthreads();
#pragma unroll
        for (int term = 0; term < 3; term++) {
            int Ab = term == 2 ? WL : WH;
            int Bb = term == 1 ? XL : XH;
#pragma unroll
            for (int k16 = 0; k16 < 2; k16++) {
                uint32_t af[5][4];
#pragma unroll
                for (int mi = 0; mi < 5; mi++)
                    ldsm4(af[mi], sb + Ab + (wm * 80 + mi * 16 + (lane & 15)) * 80 + k16 * 32 + (lane >> 4) * 16);
#pragma unroll
                for (int p = 0; p < 2; p++) {
                    uint32_t bq[4];
                    ldsm4(bq, sb + Bb + (wn * 32 + p * 16 + ((lane >> 4) & 1) * 8 + (lane & 7)) * 80
                              + k16 * 32 + ((lane >> 3) & 1) * 16);
#pragma unroll
                    for (int mi = 0; mi < 5; mi++) {
                        mma_f16(ap[mi][2 * p],     af[mi], bq);
                        mma_f16(ap[mi][2 * p + 1], af[mi], bq + 2);
                    }
                }
            }
        }
    }
    // epilogue: rows 0-31 -> f packed, 32-63 -> g packed, 64-319 -> H
#pragma unroll
    for (int mi = 0; mi < 5; mi++)
#pragma unroll
        for (int p = 0; p < 4; p++)
#pragma unroll
            for (int hf = 0; hf < 2; hf++) {
                int orow = wm * 80 + mi * 16 + hf * 8 + (lane >> 2);
                int n = nb * 128 + wn * 32 + p * 8 + 2 * (lane & 3);
                float v0 = ap[mi][p][hf * 2 + 0];
                float v1 = ap[mi][p][hf * 2 + 1];
                if (orow < 64) {
                    __half* o = orow < 32 ? d_fp : d_gp;
                    int oo = orow & 31;
                    float bz = orow < 32 ? fb[oo] : gb[oo];
                    __half h, l;
                    split2h(v0 + bz, h, l);
                    o[((size_t)b * N + n) * 64 + oo] = h;
                    o[((size_t)b * N + n) * 64 + 32 + oo] = l;
                    split2h(v1 + bz, h, l);
                    o[((size_t)b * N + n + 1) * 64 + oo] = h;
                    o[((size_t)b * N + n + 1) * 64 + 32 + oo] = l;
                } else {
                    int c = orow - 64;
                    float bz = hb[c];
                    __half2 hv = __floats2half2_rn(v0 + bz, v1 + bz);
                    *(__half2*)&d_h[((size_t)b * C + c) * N + n] = hv;
                }
            }
}

// ---------------- pass 1: Z_j via HMMA, 3-term, f double-buffered ----------------
// grid (32 jb, 8 b), 256 threads, dyn smem 62464
__global__ __launch_bounds__(256, 1) void k_zsum() {
    extern __shared__ char sm[];
    const int SGH = 0, SGL = 10240;                    // g hi/lo, fixed
    const int SFH[2] = {20480, 40960}, SFL[2] = {30720, 51200};
    const int SZ = 61440;
    uint32_t sb = smem_u32(sm);
    int tid = threadIdx.x, lane = tid & 31, w = tid >> 5;
    int jb = blockIdx.x, b = blockIdx.y;
    int wj = w & 3, wi2 = w >> 2;

    for (int t = tid; t < 1024; t += 256) {
        int row = t >> 3, p = t & 7;
        uint4 v = ((const uint4*)d_gp)[(size_t)(b * N + jb * 128 + row) * 8 + p];
        *(uint4*)(sm + (p < 4 ? SGH + row * 80 + p * 16 : SGL + row * 80 + (p - 4) * 16)) = v;
    }
    // prefetch f tile 0
    for (int t = tid; t < 1024; t += 256) {
        int row = t >> 3, p = t & 7;
        const char* src = (const char*)d_fp + ((size_t)(b * N + row) * 8 + p) * 16;
        cp16(sb + (p < 4 ? SFH[0] + row * 80 + p * 16 : SFL[0] + row * 80 + (p - 4) * 16), src);
    }
    CP_COMMIT();

    float zacc[4] = {0.f, 0.f, 0.f, 0.f};
    for (int ibt = 0; ibt < 32; ibt++) {
        int cur = ibt & 1;
        __syncthreads();
        if (ibt < 31) {
            int nxt = 1 - cur;
            for (int t = tid; t < 1024; t += 256) {
                int row = t >> 3, p = t & 7;
                const char* src = (const char*)d_fp + ((size_t)(b * N + (ibt + 1) * 128 + row) * 8 + p) * 16;
                cp16(sb + (p < 4 ? SFH[nxt] + row * 80 + p * 16 : SFL[nxt] + row * 80 + (p - 4) * 16), src);
            }
        }
        CP_COMMIT();
        CP_WAIT1();
        __syncthreads();

        float as[2][8][4] = {};
#pragma unroll
        for (int k16 = 0; k16 < 2; k16++) {
            uint32_t a0[4], a1[4];
            ldsm4(a0, sb + SGH + (wj * 32 +      (lane & 15)) * 80 + k16 * 32 + (lane >> 4) * 16);
            ldsm4(a1, sb + SGH + (wj * 32 + 16 + (lane & 15)) * 80 + k16 * 32 + (lane >> 4) * 16);
#pragma unroll
            for (int term = 0; term < 2; term++) {
                int Bb = term ? SFL[cur] : SFH[cur];
#pragma unroll
                for (int p = 0; p < 4; p++) {
                    uint32_t bq[4];
                    ldsm4(bq, sb + Bb + (wi2 * 64 + p * 16 + ((lane >> 4) & 1) * 8 + (lane & 7)) * 80
                              + k16 * 32 + ((lane >> 3) & 1) * 16);
                    mma_f16(as[0][2 * p],     a0, bq);
                    mma_f16(as[1][2 * p],     a1, bq);
                    mma_f16(as[0][2 * p + 1], a0, bq + 2);
                    mma_f16(as[1][2 * p + 1], a1, bq + 2);
                }
            }
            ldsm4(a0, sb + SGL + (wj * 32 +      (lane & 15)) * 80 + k16 * 32 + (lane >> 4) * 16);
            ldsm4(a1, sb + SGL + (wj * 32 + 16 + (lane & 15)) * 80 + k16 * 32 + (lane >> 4) * 16);
#pragma unroll
            for (int p = 0; p < 4; p++) {
                uint32_t bq[4];
                ldsm4(bq, sb + SFH[cur] + (wi2 * 64 + p * 16 + ((lane >> 4) & 1) * 8 + (lane & 7)) * 80
                          + k16 * 32 + ((lane >> 3) & 1) * 16);
                mma_f16(as[0][2 * p],     a0, bq);
                mma_f16(as[1][2 * p],     a1, bq);
                mma_f16(as[0][2 * p + 1], a0, bq + 2);
                mma_f16(as[1][2 * p + 1], a1, bq + 2);
            }
        }
#pragma unroll
        for (int mh = 0; mh < 2; mh++)
#pragma unroll
            for (int n8 = 0; n8 < 8; n8++) {
                zacc[mh * 2 + 0] += __expf(as[mh][n8][0]) + __expf(as[mh][n8][1]);
                zacc[mh * 2 + 1] += __expf(as[mh][n8][2]) + __expf(as[mh][n8][3]);
            }
    }
#pragma unroll
    for (int m = 0; m < 4; m++) {
        float v = zacc[m];
        v += __shfl_xor_sync(0xffffffffu, v, 1);
        v += __shfl_xor_sync(0xffffffffu, v, 2);
        if ((lane & 3) == 0) {
            int jloc = wj * 32 + (m >> 1) * 16 + (m & 1) * 8 + (lane >> 2);
            *(float*)(sm + SZ + (wi2 * 128 + jloc) * 4) = v;
        }
    }
    __syncthreads();
    if (tid < 128) {
        float z = *(float*)(sm + SZ + tid * 4) + *(float*)(sm + SZ + (128 + tid) * 4);
        d_rz[b * N + jb * 128 + tid] = 1.f / z;
    }
}

// ---------------- pass 2: S (3-term) -> exp*rz -> E fp16 -> O (1-term), H double-buffered ----------------
// grid (32 ib, 8 b), 256 threads, dyn smem 215552
__global__ __launch_bounds__(256, 1) void k_out(const float* __restrict__ x, float* __restrict__ out) {
    extern __shared__ char sm[];
    const int SFH = 0, SFL = 10240, SGH = 20480, SGL = 30720;
    const int SE = 40960;                       // 128*272
    const int SHB[2] = {75776, 145408};         // 2 x 256*272
    const int SR = 215040;
    uint32_t sb = smem_u32(sm);
    int tid = threadIdx.x, lane = tid & 31, w = tid >> 5;
    int ib = blockIdx.x, b = blockIdx.y;
    int wa = w & 3, wb = w >> 2;   // S phase: i-quarter / j-half

    for (int t = tid; t < 1024; t += 256) {
        int row = t >> 3, p = t & 7;
        uint4 v = ((const uint4*)d_fp)[(size_t)(b * N + ib * 128 + row) * 8 + p];
        *(uint4*)(sm + (p < 4 ? SFH + row * 80 + p * 16 : SFL + row * 80 + (p - 4) * 16)) = v;
    }
    // prefetch H tile 0
    for (int t = tid; t < 4096; t += 256) {
        int row = t >> 4, u = t & 15;
        const char* src = (const char*)d_h + ((size_t)(b * C + row) * N + u * 8) * 2;
        cp16(sb + SHB[0] + row * 272 + u * 16, src);
    }
    CP_COMMIT();

    float ao[2][16][4] = {};
    for (int jb = 0; jb < 32; jb++) {
        int cur = jb & 1;
        __syncthreads();
        // g tile (cur) via cp.async — group committed BEFORE H-next so wait_group 1 drains it
        for (int t = tid; t < 1024; t += 256) {
            int row = t >> 3, p = t & 7;
            const char* src = (const char*)d_gp + ((size_t)(b * N + jb * 128 + row) * 8 + p) * 16;
            cp16(sb + (p < 4 ? SGH + row * 80 + p * 16 : SGL + row * 80 + (p - 4) * 16), src);
        }
        CP_COMMIT();
        if (jb < 31) {
            int nxt = 1 - cur;
            for (int t = tid; t < 4096; t += 256) {
                int row = t >> 4, u = t & 15;
                const char* src = (const char*)d_h + ((size_t)(b * C + row) * N + (jb + 1) * 128 + u * 8) * 2;
                cp16(sb + SHB[nxt] + row * 272 + u * 16, src);
            }
        }
        CP_COMMIT();
        if (tid < 128) *(float*)(sm + SR + tid * 4) = d_rz[b * N + jb * 128 + tid];
        CP_WAIT1();
        __syncthreads();

        // --- S tile (3 terms) ---
        float as[2][8][4] = {};
#pragma unroll
        for (int k16 = 0; k16 < 2; k16++) {
            uint32_t a0[4], a1[4];
            ldsm4(a0, sb + SFH + (wa * 32 +      (lane & 15)) * 80 + k16 * 32 + (lane >> 4) * 16);
            ldsm4(a1, sb + SFH + (wa * 32 + 16 + (lane & 15)) * 80 + k16 * 32 + (lane >> 4) * 16);
#pragma unroll
            for (int term = 0; term < 2; term++) {
                int Bb = term ? SGL : SGH;
#pragma unroll
                for (int p = 0; p < 4; p++) {
                    uint32_t bq[4];
                    ldsm4(bq, sb + Bb + (wb * 64 + p * 16 + ((lane >> 4) & 1) * 8 + (lane & 7)) * 80
                              + k16 * 32 + ((lane >> 3) & 1) * 16);
                    mma_f16(as[0][2 * p],     a0, bq);
                    mma_f16(as[1][2 * p],     a1, bq);
                    mma_f16(as[0][2 * p + 1], a0, bq + 2);
                    mma_f16(as[1][2 * p + 1], a1, bq + 2);
                }
            }
            ldsm4(a0, sb + SFL + (wa * 32 +      (lane & 15)) * 80 + k16 * 32 + (lane >> 4) * 16);
            ldsm4(a1, sb + SFL + (wa * 32 + 16 + (lane & 15)) * 80 + k16 * 32 + (lane >> 4) * 16);
#pragma unroll
            for (int p = 0; p < 4; p++) {
                uint32_t bq[4];
                ldsm4(bq, sb + SGH + (wb * 64 + p * 16 + ((lane >> 4) & 1) * 8 + (lane & 7)) * 80
                          + k16 * 32 + ((lane >> 3) & 1) * 16);
                mma_f16(as[0][2 * p],     a0, bq);
                mma_f16(as[1][2 * p],     a1, bq);
                mma_f16(as[0][2 * p + 1], a0, bq + 2);
                mma_f16(as[1][2 * p + 1], a1, bq + 2);
            }
        }
        // --- E = exp(S) * rz_j -> fp16 ---
#pragma unroll
        for (int mh = 0; mh < 2; mh++)
#pragma unroll
            for (int n8 = 0; n8 < 8; n8++) {
                int irow = wa * 32 + mh * 16 + (lane >> 2);
                int jcol = wb * 64 + n8 * 8 + 2 * (lane & 3);
                float2 rzv = *(float2*)(sm + SR + jcol * 4);
#pragma unroll
                for (int hh = 0; hh < 2; hh++) {
                    float e0 = __expf(as[mh][n8][hh * 2 + 0]) * rzv.x;
                    float e1 = __expf(as[mh][n8][hh * 2 + 1]) * rzv.y;
                    __half2 hp = __floats2half2_rn(e0, e1);
                    *(uint32_t*)(sm + SE + (irow + hh * 8) * 272 + jcol * 2) = *(uint32_t*)&hp;
                }
            }
        __syncthreads();

        // --- O tile: A = H rows c (w*32..), B = E rows i, k = j ---
        int SH = SHB[cur];
#pragma unroll
        for (int k16 = 0; k16 < 8; k16++) {
            uint32_t a0[4], a1[4];
            ldsm4(a0, sb + SH + (w * 32 +      (lane & 15)) * 272 + k16 * 32 + (lane >> 4) * 16);
            ldsm4(a1, sb + SH + (w * 32 + 16 + (lane & 15)) * 272 + k16 * 32 + (lane >> 4) * 16);
#pragma unroll
            for (int p = 0; p < 8; p++) {
                uint32_t bq[4];
                ldsm4(bq, sb + SE + (p * 16 + ((lane >> 4) & 1) * 8 + (lane & 7)) * 272
                          + k16 * 32 + ((lane >> 3) & 1) * 16);
                mma_f16(ao[0][2 * p],     a0, bq);
                mma_f16(ao[1][2 * p],     a1, bq);
                mma_f16(ao[0][2 * p + 1], a0, bq + 2);
                mma_f16(ao[1][2 * p + 1], a1, bq + 2);
            }
        }
    }

    // epilogue: out[b][c][i] = O + x
#pragma unroll
    for (int mh = 0; mh < 2; mh++)
#pragma unroll
        for (int n8 = 0; n8 < 16; n8++) {
            int c = w * 32 + mh * 16 + (lane >> 2);
            int icol = ib * 128 + n8 * 8 + 2 * (lane & 3);
            size_t idx = (size_t)(b * C + c) * N + icol;
            float2 xv = *(const float2*)&x[idx];
            *(float2*)&out[idx] = make_float2(ao[mh][n8][0] + xv.x, ao[mh][n8][1] + xv.y);
            idx += (size_t)8 * N;
            xv = *(const float2*)&x[idx];
            *(float2*)&out[idx] = make_float2(ao[mh][n8][2] + xv.x, ao[mh][n8][3] + xv.y);
        }
}

// ---------------- launch ----------------
extern "C" void kernel_launch(void* const* d_in, const int* in_sizes, int n_in,
                              void* d_out, int out_size) {
    const float* x  = (const float*)d_in[0];
    const float* fw = (const float*)d_in[1];
    const float* fb = (const float*)d_in[2];
    const float* gw = (const float*)d_in[3];
    const float* gb = (const float*)d_in[4];
    const float* hw = (const float*)d_in[5];
    const float* hb = (const float*)d_in[6];
    float* out = (float*)d_out;

    const int SM_P = 71680;
    const int SM_Z = 62464;
    const int SM_O = 215552;
    cudaFuncSetAttribute(k_proj, cudaFuncAttributeMaxDynamicSharedMemorySize, SM_P);
    cudaFuncSetAttribute(k_zsum, cudaFuncAttributeMaxDynamicSharedMemorySize, SM_Z);
    cudaFuncSetAttribute(k_out,  cudaFuncAttributeMaxDynamicSharedMemorySize, SM_O);

    k_prep<<<160, 512>>>(fw, gw, hw);
    k_proj<<<dim3(32, 8), 512, SM_P>>>(x, fb, gb, hb);
    k_zsum<<<dim3(32, 8), 256, SM_Z>>>();
    k_out<<<dim3(32, 8), 256, SM_O>>>(x, out);
}

// round 12
// speedup vs baseline: 5.8116x; 1.0480x over previous
#include <cuda_runtime.h>
#include <cuda_fp16.h>
#include <cstdint>
#include <math.h>

#define Bn 8
#define C  256
#define N  4096

// ---------------- scratch ----------------
__device__ __half d_fp[Bn * N * 64];            // f packed fp16 [b][n][hi k0..31 | lo k0..31]
__device__ __half d_gp[Bn * N * 64];            // g packed
__device__ __half d_h [(size_t)Bn * C * N];     // H = h_w x + h_b, fp16 [b][c][j] (NOT Z-scaled)
__device__ __half d_wh[320 * 256];              // W = [fw;gw;hw] split hi
__device__ __half d_wl[320 * 256];              // W split lo
__device__ float d_rz[Bn * N];                  // 1/Z_j

// ---------------- helpers ----------------
__device__ __forceinline__ uint32_t smem_u32(const void* p) {
    uint32_t a;
    asm("{ .reg .u64 t; cvta.to.shared.u64 t, %1; cvt.u32.u64 %0, t; }" : "=r"(a) : "l"(p));
    return a;
}
__device__ __forceinline__ void ldsm4(uint32_t* r, uint32_t a) {
    asm volatile("ldmatrix.sync.aligned.m8n8.x4.shared.b16 {%0,%1,%2,%3}, [%4];"
        : "=r"(r[0]), "=r"(r[1]), "=r"(r[2]), "=r"(r[3]) : "r"(a));
}
__device__ __forceinline__ void mma_f16(float* d, const uint32_t* a, const uint32_t* b) {
    asm volatile("mma.sync.aligned.m16n8k16.row.col.f32.f16.f16.f32 "
        "{%0,%1,%2,%3}, {%4,%5,%6,%7}, {%8,%9}, {%0,%1,%2,%3};"
        : "+f"(d[0]), "+f"(d[1]), "+f"(d[2]), "+f"(d[3])
        : "r"(a[0]), "r"(a[1]), "r"(a[2]), "r"(a[3]), "r"(b[0]), "r"(b[1]));
}
__device__ __forceinline__ void split2h(float v, __half& h, __half& l) {
    h = __float2half_rn(v);
    l = __float2half_rn(v - __half2float(h));
}
__device__ __forceinline__ void cp16(uint32_t dst, const void* src) {
    asm volatile("cp.async.cg.shared.global [%0], [%1], 16;" :: "r"(dst), "l"(src));
}
#define CP_COMMIT() asm volatile("cp.async.commit_group;" ::: "memory")
#define CP_WAIT0()  asm volatile("cp.async.wait_group 0;" ::: "memory")
#define CP_WAIT1()  asm volatile("cp.async.wait_group 1;" ::: "memory")
#define BAR_GRP(id) asm volatile("bar.sync %0, 128;" :: "r"(id) : "memory")

// ---------------- W pre-split: [fw;gw;hw] -> packed fp16 hi/lo ----------------
__global__ __launch_bounds__(512) void k_prep(const float* __restrict__ fw,
                                              const float* __restrict__ gw,
                                              const float* __restrict__ hw) {
    int idx = blockIdx.x * 512 + threadIdx.x;   // 81920
    int row = idx >> 8, cc = idx & 255;
    const float* wp = row < 32 ? fw + row * 256
                     : row < 64 ? gw + (row - 32) * 256
                                : hw + (row - 64) * 256;
    __half h, l;
    split2h(wp[cc], h, l);
    d_wh[idx] = h;
    d_wl[idx] = l;
}

// ---------------- merged projections via 3-term fp16 HMMA, W tiles via cp.async ----------------
// grid (32 nb, 8 b), 512 threads, dyn smem 71680
__global__ __launch_bounds__(512, 1) void k_proj(
    const float* __restrict__ x,
    const float* __restrict__ fb, const float* __restrict__ gb, const float* __restrict__ hb) {
    extern __shared__ char sm[];
    const int WH = 0, WL = 25600, XH = 51200, XL = 61440;
    uint32_t sb = smem_u32(sm);
    int tid = threadIdx.x, lane = tid & 31, w = tid >> 5;
    int nb = blockIdx.x, b = blockIdx.y;
    int wm = w & 3, wn = w >> 2;
    float ap[5][4][4] = {};

    for (int c0 = 0; c0 < 256; c0 += 32) {
        __syncthreads();
        for (int t = tid; t < 1280; t += 512) {
            int row = t >> 2, p = t & 3;
            cp16(sb + WH + row * 80 + p * 16, (const char*)d_wh + (row * 256 + c0 + p * 8) * 2);
            cp16(sb + WL + row * 80 + p * 16, (const char*)d_wl + (row * 256 + c0 + p * 8) * 2);
        }
        CP_COMMIT();
        for (int idx = tid; idx < 4096; idx += 512) {
            int cc = idx >> 7, n = idx & 127;
            __half h, l;
            split2h(x[((size_t)b * 256 + c0 + cc) * 4096 + nb * 128 + n], h, l);
            *(__half*)(sm + XH + n * 80 + cc * 2) = h;
            *(__half*)(sm + XL + n * 80 + cc * 2) = l;
        }
        CP_WAIT0();
        __syncthreads();
#pragma unroll
        for (int term = 0; term < 3; term++) {
            int Ab = term == 2 ? WL : WH;
            int Bb = term == 1 ? XL : XH;
#pragma unroll
            for (int k16 = 0; k16 < 2; k16++) {
                uint32_t af[5][4];
#pragma unroll
                for (int mi = 0; mi < 5; mi++)
                    ldsm4(af[mi], sb + Ab + (wm * 80 + mi * 16 + (lane & 15)) * 80 + k16 * 32 + (lane >> 4) * 16);
#pragma unroll
                for (int p = 0; p < 2; p++) {
                    uint32_t bq[4];
                    ldsm4(bq, sb + Bb + (wn * 32 + p * 16 + ((lane >> 4) & 1) * 8 + (lane & 7)) * 80
                              + k16 * 32 + ((lane >> 3) & 1) * 16);
#pragma unroll
                    for (int mi = 0; mi < 5; mi++) {
                        mma_f16(ap[mi][2 * p],     af[mi], bq);
                        mma_f16(ap[mi][2 * p + 1], af[mi], bq + 2);
                    }
                }
            }
        }
    }
#pragma unroll
    for (int mi = 0; mi < 5; mi++)
#pragma unroll
        for (int p = 0; p < 4; p++)
#pragma unroll
            for (int hf = 0; hf < 2; hf++) {
                int orow = wm * 80 + mi * 16 + hf * 8 + (lane >> 2);
                int n = nb * 128 + wn * 32 + p * 8 + 2 * (lane & 3);
                float v0 = ap[mi][p][hf * 2 + 0];
                float v1 = ap[mi][p][hf * 2 + 1];
                if (orow < 64) {
                    __half* o = orow < 32 ? d_fp : d_gp;
                    int oo = orow & 31;
                    float bz = orow < 32 ? fb[oo] : gb[oo];
                    __half h, l;
                    split2h(v0 + bz, h, l);
                    o[((size_t)b * N + n) * 64 + oo] = h;
                    o[((size_t)b * N + n) * 64 + 32 + oo] = l;
                    split2h(v1 + bz, h, l);
                    o[((size_t)b * N + n + 1) * 64 + oo] = h;
                    o[((size_t)b * N + n + 1) * 64 + 32 + oo] = l;
                } else {
                    int c = orow - 64;
                    float bz = hb[c];
                    __half2 hv = __floats2half2_rn(v0 + bz, v1 + bz);
                    *(__half2*)&d_h[((size_t)b * C + c) * N + n] = hv;
                }
            }
}

// ---------------- pass 1: Z_j via HMMA, 3-term, f double-buffered ----------------
// grid (32 jb, 8 b), 256 threads, dyn smem 62464
__global__ __launch_bounds__(256, 1) void k_zsum() {
    extern __shared__ char sm[];
    const int SGH = 0, SGL = 10240;
    const int SFH[2] = {20480, 40960}, SFL[2] = {30720, 51200};
    const int SZ = 61440;
    uint32_t sb = smem_u32(sm);
    int tid = threadIdx.x, lane = tid & 31, w = tid >> 5;
    int jb = blockIdx.x, b = blockIdx.y;
    int wj = w & 3, wi2 = w >> 2;

    for (int t = tid; t < 1024; t += 256) {
        int row = t >> 3, p = t & 7;
        uint4 v = ((const uint4*)d_gp)[(size_t)(b * N + jb * 128 + row) * 8 + p];
        *(uint4*)(sm + (p < 4 ? SGH + row * 80 + p * 16 : SGL + row * 80 + (p - 4) * 16)) = v;
    }
    for (int t = tid; t < 1024; t += 256) {
        int row = t >> 3, p = t & 7;
        const char* src = (const char*)d_fp + ((size_t)(b * N + row) * 8 + p) * 16;
        cp16(sb + (p < 4 ? SFH[0] + row * 80 + p * 16 : SFL[0] + row * 80 + (p - 4) * 16), src);
    }
    CP_COMMIT();

    float zacc[4] = {0.f, 0.f, 0.f, 0.f};
    for (int ibt = 0; ibt < 32; ibt++) {
        int cur = ibt & 1;
        __syncthreads();
        if (ibt < 31) {
            int nxt = 1 - cur;
            for (int t = tid; t < 1024; t += 256) {
                int row = t >> 3, p = t & 7;
                const char* src = (const char*)d_fp + ((size_t)(b * N + (ibt + 1) * 128 + row) * 8 + p) * 16;
                cp16(sb + (p < 4 ? SFH[nxt] + row * 80 + p * 16 : SFL[nxt] + row * 80 + (p - 4) * 16), src);
            }
        }
        CP_COMMIT();
        CP_WAIT1();
        __syncthreads();

        float as[2][8][4] = {};
#pragma unroll
        for (int k16 = 0; k16 < 2; k16++) {
            uint32_t a0[4], a1[4];
            ldsm4(a0, sb + SGH + (wj * 32 +      (lane & 15)) * 80 + k16 * 32 + (lane >> 4) * 16);
            ldsm4(a1, sb + SGH + (wj * 32 + 16 + (lane & 15)) * 80 + k16 * 32 + (lane >> 4) * 16);
#pragma unroll
            for (int term = 0; term < 2; term++) {
                int Bb = term ? SFL[cur] : SFH[cur];
#pragma unroll
                for (int p = 0; p < 4; p++) {
                    uint32_t bq[4];
                    ldsm4(bq, sb + Bb + (wi2 * 64 + p * 16 + ((lane >> 4) & 1) * 8 + (lane & 7)) * 80
                              + k16 * 32 + ((lane >> 3) & 1) * 16);
                    mma_f16(as[0][2 * p],     a0, bq);
                    mma_f16(as[1][2 * p],     a1, bq);
                    mma_f16(as[0][2 * p + 1], a0, bq + 2);
                    mma_f16(as[1][2 * p + 1], a1, bq + 2);
                }
            }
            ldsm4(a0, sb + SGL + (wj * 32 +      (lane & 15)) * 80 + k16 * 32 + (lane >> 4) * 16);
            ldsm4(a1, sb + SGL + (wj * 32 + 16 + (lane & 15)) * 80 + k16 * 32 + (lane >> 4) * 16);
#pragma unroll
            for (int p = 0; p < 4; p++) {
                uint32_t bq[4];
                ldsm4(bq, sb + SFH[cur] + (wi2 * 64 + p * 16 + ((lane >> 4) & 1) * 8 + (lane & 7)) * 80
                          + k16 * 32 + ((lane >> 3) & 1) * 16);
                mma_f16(as[0][2 * p],     a0, bq);
                mma_f16(as[1][2 * p],     a1, bq);
                mma_f16(as[0][2 * p + 1], a0, bq + 2);
                mma_f16(as[1][2 * p + 1], a1, bq + 2);
            }
        }
#pragma unroll
        for (int mh = 0; mh < 2; mh++)
#pragma unroll
            for (int n8 = 0; n8 < 8; n8++) {
                zacc[mh * 2 + 0] += __expf(as[mh][n8][0]) + __expf(as[mh][n8][1]);
                zacc[mh * 2 + 1] += __expf(as[mh][n8][2]) + __expf(as[mh][n8][3]);
            }
    }
#pragma unroll
    for (int m = 0; m < 4; m++) {
        float v = zacc[m];
        v += __shfl_xor_sync(0xffffffffu, v, 1);
        v += __shfl_xor_sync(0xffffffffu, v, 2);
        if ((lane & 3) == 0) {
            int jloc = wj * 32 + (m >> 1) * 16 + (m & 1) * 8 + (lane >> 2);
            *(float*)(sm + SZ + (wi2 * 128 + jloc) * 4) = v;
        }
    }
    __syncthreads();
    if (tid < 128) {
        float z = *(float*)(sm + SZ + tid * 4) + *(float*)(sm + SZ + (128 + tid) * 4);
        d_rz[b * N + jb * 128 + tid] = 1.f / z;
    }
}

// ---------------- pass 2 (group-split): S -> exp*rz -> E(group-local) -> O, out = O + x ----------------
// grid (32 ib, 8 b), 256 threads (2 groups x 4 warps), dyn smem 231424
__global__ __launch_bounds__(256, 1) void k_out(const float* __restrict__ x, float* __restrict__ out) {
    extern __shared__ char sm[];
    const int SFH = 0, SFL = 10240, SGH = 20480, SGL = 30720;
    const int SE = 40960;                       // E [128][272] group-local halves
    const int SHB[2] = {75776, 145408};         // 2 x H [256][272]
    const int SR = 215040;                      // rz for whole batch b: 16KB
    uint32_t sb = smem_u32(sm);
    int tid = threadIdx.x, lane = tid & 31, w = tid >> 5;
    int ib = blockIdx.x, b = blockIdx.y;
    int grp = w >> 2, wq = w & 3;
    int i0 = grp * 64 + wq * 16;    // S phase: this warp's 16 i rows

    // prologue: cp g(0), H(0), H(1); direct f + rz
    for (int t = tid; t < 1024; t += 256) {
        int row = t >> 3, p = t & 7;
        const char* src = (const char*)d_gp + ((size_t)(b * N + row) * 8 + p) * 16;
        cp16(sb + (p < 4 ? SGH + row * 80 + p * 16 : SGL + row * 80 + (p - 4) * 16), src);
    }
    CP_COMMIT();
    for (int t = tid; t < 4096; t += 256) {
        int row = t >> 4, u = t & 15;
        cp16(sb + SHB[0] + row * 272 + u * 16,
             (const char*)d_h + ((size_t)(b * C + row) * N + u * 8) * 2);
    }
    CP_COMMIT();
    for (int t = tid; t < 4096; t += 256) {
        int row = t >> 4, u = t & 15;
        cp16(sb + SHB[1] + row * 272 + u * 16,
             (const char*)d_h + ((size_t)(b * C + row) * N + 128 + u * 8) * 2);
    }
    CP_COMMIT();
    for (int t = tid; t < 1024; t += 256) {
        int row = t >> 3, p = t & 7;
        uint4 v = ((const uint4*)d_fp)[(size_t)(b * N + ib * 128 + row) * 8 + p];
        *(uint4*)(sm + (p < 4 ? SFH + row * 80 + p * 16 : SFL + row * 80 + (p - 4) * 16)) = v;
    }
    for (int t = tid; t < 1024; t += 256)
        ((float4*)(sm + SR))[t] = ((const float4*)(d_rz + (size_t)b * N))[t];

    float ao[4][8][4] = {};   // O: c = wq*64 + mi*16.., i = grp*64 + n*8..
    for (int jb = 0; jb < 32; jb++) {
        if (jb == 31) { CP_WAIT0(); } else { CP_WAIT1(); }  // tail: drain g(31) too
        __syncthreads();       // bar1: g/H visible, prev O done reading E

        // --- S: this warp's 16 i x 128 j (3 terms) ---
        float as[16][4] = {};
#pragma unroll
        for (int k16 = 0; k16 < 2; k16++) {
            uint32_t ah[4], al[4];
            ldsm4(ah, sb + SFH + (i0 + (lane & 15)) * 80 + k16 * 32 + (lane >> 4) * 16);
            ldsm4(al, sb + SFL + (i0 + (lane & 15)) * 80 + k16 * 32 + (lane >> 4) * 16);
#pragma unroll
            for (int p = 0; p < 8; p++) {
                uint32_t bh[4], bl[4];
                ldsm4(bh, sb + SGH + (p * 16 + ((lane >> 4) & 1) * 8 + (lane & 7)) * 80
                          + k16 * 32 + ((lane >> 3) & 1) * 16);
                mma_f16(as[2 * p],     ah, bh);
                mma_f16(as[2 * p + 1], ah, bh + 2);
                mma_f16(as[2 * p],     al, bh);
                mma_f16(as[2 * p + 1], al, bh + 2);
                ldsm4(bl, sb + SGL + (p * 16 + ((lane >> 4) & 1) * 8 + (lane & 7)) * 80
                          + k16 * 32 + ((lane >> 3) & 1) * 16);
                mma_f16(as[2 * p],     ah, bl);
                mma_f16(as[2 * p + 1], ah, bl + 2);
            }
        }
        // --- E = exp(S) * rz -> fp16 (group-local rows) ---
#pragma unroll
        for (int n8 = 0; n8 < 16; n8++) {
            int jcol = n8 * 8 + 2 * (lane & 3);
            float2 rzv = *(float2*)(sm + SR + (jb * 128 + jcol) * 4);
#pragma unroll
            for (int hh = 0; hh < 2; hh++) {
                float e0 = __expf(as[n8][hh * 2 + 0]) * rzv.x;
                float e1 = __expf(as[n8][hh * 2 + 1]) * rzv.y;
                __half2 hp = __floats2half2_rn(e0, e1);
                *(uint32_t*)(sm + SE + (i0 + hh * 8 + (lane >> 2)) * 272 + jcol * 2) = *(uint32_t*)&hp;
            }
        }
        BAR_GRP(grp + 1);      // group-local: our E half complete

        // --- O: A = H rows c (wq*64..+64), B = E rows i (grp*64..+64), k = j ---
        int SH = SHB[jb & 1];
#pragma unroll
        for (int k16 = 0; k16 < 8; k16++) {
            uint32_t af[4][4];
#pragma unroll
            for (int mi = 0; mi < 4; mi++)
                ldsm4(af[mi], sb + SH + (wq * 64 + mi * 16 + (lane & 15)) * 272 + k16 * 32 + (lane >> 4) * 16);
#pragma unroll
            for (int p2 = 0; p2 < 4; p2++) {
                uint32_t bq[4];
                ldsm4(bq, sb + SE + (grp * 64 + p2 * 16 + ((lane >> 4) & 1) * 8 + (lane & 7)) * 272
                          + k16 * 32 + ((lane >> 3) & 1) * 16);
#pragma unroll
                for (int mi = 0; mi < 4; mi++) {
                    mma_f16(ao[mi][2 * p2],     af[mi], bq);
                    mma_f16(ao[mi][2 * p2 + 1], af[mi], bq + 2);
                }
            }
        }
        __syncthreads();       // bar2: O reads of g/E/H(cur) done; buffers reusable

        if (jb < 31) {
            for (int t = tid; t < 1024; t += 256) {
                int row = t >> 3, p = t & 7;
                const char* src = (const char*)d_gp + ((size_t)(b * N + (jb + 1) * 128 + row) * 8 + p) * 16;
                cp16(sb + (p < 4 ? SGH + row * 80 + p * 16 : SGL + row * 80 + (p - 4) * 16), src);
            }
            CP_COMMIT();
        }
        if (jb < 30) {
            for (int t = tid; t < 4096; t += 256) {
                int row = t >> 4, u = t & 15;
                cp16(sb + SHB[jb & 1] + row * 272 + u * 16,
                     (const char*)d_h + ((size_t)(b * C + row) * N + (jb + 2) * 128 + u * 8) * 2);
            }
            CP_COMMIT();
        }
    }

    // epilogue: out[b][c][i] = O + x
#pragma unroll
    for (int mi = 0; mi < 4; mi++)
#pragma unroll
        for (int n = 0; n < 8; n++) {
            int c = wq * 64 + mi * 16 + (lane >> 2);
            int icol = ib * 128 + grp * 64 + n * 8 + 2 * (lane & 3);
            size_t idx = (size_t)(b * C + c) * N + icol;
            float2 xv = *(const float2*)&x[idx];
            *(float2*)&out[idx] = make_float2(ao[mi][n][0] + xv.x, ao[mi][n][1] + xv.y);
            idx += (size_t)8 * N;
            xv = *(const float2*)&x[idx];
            *(float2*)&out[idx] = make_float2(ao[mi][n][2] + xv.x, ao[mi][n][3] + xv.y);
        }
}

// ---------------- launch ----------------
extern "C" void kernel_launch(void* const* d_in, const int* in_sizes, int n_in,
                              void* d_out, int out_size) {
    const float* x  = (const float*)d_in[0];
    const float* fw = (const float*)d_in[1];
    const float* fb = (const float*)d_in[2];
    const float* gw = (const float*)d_in[3];
    const float* gb = (const float*)d_in[4];
    const float* hw = (const float*)d_in[5];
    const float* hb = (const float*)d_in[6];
    float* out = (float*)d_out;

    const int SM_P = 71680;
    const int SM_Z = 62464;
    const int SM_O = 231424;
    cudaFuncSetAttribute(k_proj, cudaFuncAttributeMaxDynamicSharedMemorySize, SM_P);
    cudaFuncSetAttribute(k_zsum, cudaFuncAttributeMaxDynamicSharedMemorySize, SM_Z);
    cudaFuncSetAttribute(k_out,  cudaFuncAttributeMaxDynamicSharedMemorySize, SM_O);

    k_prep<<<160, 512>>>(fw, gw, hw);
    k_proj<<<dim3(32, 8), 512, SM_P>>>(x, fb, gb, hb);
    k_zsum<<<dim3(32, 8), 256, SM_Z>>>();
    k_out<<<dim3(32, 8), 256, SM_O>>>(x, out);
}

// round 14
// speedup vs baseline: 5.9314x; 1.0206x over previous
#include <cuda_runtime.h>
#include <cuda_fp16.h>
#include <cstdint>
#include <math.h>

#define Bn 8
#define C  256
#define N  4096

// ---------------- scratch ----------------
__device__ __half d_fp[Bn * N * 64];            // f packed fp16 [b][n][hi k0..31 | lo k0..31]
__device__ __half d_gp[Bn * N * 64];            // g packed
__device__ __half d_h [(size_t)Bn * C * N];     // H = h_w x + h_b, fp16 [b][c][j] (NOT Z-scaled)
__device__ __half d_wh[320 * 256];              // W = [fw;gw;hw] split hi
__device__ __half d_wl[320 * 256];              // W split lo
__device__ float d_rz[Bn * N];                  // 1/Z_j

// ---------------- helpers ----------------
__device__ __forceinline__ uint32_t smem_u32(const void* p) {
    uint32_t a;
    asm("{ .reg .u64 t; cvta.to.shared.u64 t, %1; cvt.u32.u64 %0, t; }" : "=r"(a) : "l"(p));
    return a;
}
__device__ __forceinline__ void ldsm4(uint32_t* r, uint32_t a) {
    asm volatile("ldmatrix.sync.aligned.m8n8.x4.shared.b16 {%0,%1,%2,%3}, [%4];"
        : "=r"(r[0]), "=r"(r[1]), "=r"(r[2]), "=r"(r[3]) : "r"(a));
}
__device__ __forceinline__ void mma_f16(float* d, const uint32_t* a, const uint32_t* b) {
    asm volatile("mma.sync.aligned.m16n8k16.row.col.f32.f16.f16.f32 "
        "{%0,%1,%2,%3}, {%4,%5,%6,%7}, {%8,%9}, {%0,%1,%2,%3};"
        : "+f"(d[0]), "+f"(d[1]), "+f"(d[2]), "+f"(d[3])
        : "r"(a[0]), "r"(a[1]), "r"(a[2]), "r"(a[3]), "r"(b[0]), "r"(b[1]));
}
__device__ __forceinline__ void split2h(float v, __half& h, __half& l) {
    h = __float2half_rn(v);
    l = __float2half_rn(v - __half2float(h));
}
__device__ __forceinline__ void cp16(uint32_t dst, const void* src) {
    asm volatile("cp.async.cg.shared.global [%0], [%1], 16;" :: "r"(dst), "l"(src));
}
#define CP_COMMIT() asm volatile("cp.async.commit_group;" ::: "memory")
#define CP_WAIT0()  asm volatile("cp.async.wait_group 0;" ::: "memory")
#define CP_WAIT1()  asm volatile("cp.async.wait_group 1;" ::: "memory")
#define BAR_GRP(id) asm volatile("bar.sync %0, 128;" :: "r"(id) : "memory")

// ---------------- W pre-split: [fw;gw;hw] -> packed fp16 hi/lo ----------------
__global__ __launch_bounds__(512) void k_prep(const float* __restrict__ fw,
                                              const float* __restrict__ gw,
                                              const float* __restrict__ hw) {
    int idx = blockIdx.x * 512 + threadIdx.x;   // 81920
    int row = idx >> 8, cc = idx & 255;
    const float* wp = row < 32 ? fw + row * 256
                     : row < 64 ? gw + (row - 32) * 256
                                : hw + (row - 64) * 256;
    __half h, l;
    split2h(wp[cc], h, l);
    d_wh[idx] = h;
    d_wl[idx] = l;
}

// ---------------- merged projections via 3-term fp16 HMMA, W tiles via cp.async ----------------
// grid (32 nb, 8 b), 512 threads, dyn smem 71680
__global__ __launch_bounds__(512, 1) void k_proj(
    const float* __restrict__ x,
    const float* __restrict__ fb, const float* __restrict__ gb, const float* __restrict__ hb) {
    extern __shared__ char sm[];
    const int WH = 0, WL = 25600, XH = 51200, XL = 61440;
    uint32_t sb = smem_u32(sm);
    int tid = threadIdx.x, lane = tid & 31, w = tid >> 5;
    int nb = blockIdx.x, b = blockIdx.y;
    int wm = w & 3, wn = w >> 2;
    float ap[5][4][4] = {};

    for (int c0 = 0; c0 < 256; c0 += 32) {
        __syncthreads();
        for (int t = tid; t < 1280; t += 512) {
            int row = t >> 2, p = t & 3;
            cp16(sb + WH + row * 80 + p * 16, (const char*)d_wh + (row * 256 + c0 + p * 8) * 2);
            cp16(sb + WL + row * 80 + p * 16, (const char*)d_wl + (row * 256 + c0 + p * 8) * 2);
        }
        CP_COMMIT();
        for (int idx = tid; idx < 4096; idx += 512) {
            int cc = idx >> 7, n = idx & 127;
            __half h, l;
            split2h(x[((size_t)b * 256 + c0 + cc) * 4096 + nb * 128 + n], h, l);
            *(__half*)(sm + XH + n * 80 + cc * 2) = h;
            *(__half*)(sm + XL + n * 80 + cc * 2) = l;
        }
        CP_WAIT0();
        __syncthreads();
#pragma unroll
        for (int term = 0; term < 3; term++) {
            int Ab = term == 2 ? WL : WH;
            int Bb = term == 1 ? XL : XH;
#pragma unroll
            for (int k16 = 0; k16 < 2; k16++) {
                uint32_t af[5][4];
#pragma unroll
                for (int mi = 0; mi < 5; mi++)
                    ldsm4(af[mi], sb + Ab + (wm * 80 + mi * 16 + (lane & 15)) * 80 + k16 * 32 + (lane >> 4) * 16);
#pragma unroll
                for (int p = 0; p < 2; p++) {
                    uint32_t bq[4];
                    ldsm4(bq, sb + Bb + (wn * 32 + p * 16 + ((lane >> 4) & 1) * 8 + (lane & 7)) * 80
                              + k16 * 32 + ((lane >> 3) & 1) * 16);
#pragma unroll
                    for (int mi = 0; mi < 5; mi++) {
                        mma_f16(ap[mi][2 * p],     af[mi], bq);
                        mma_f16(ap[mi][2 * p + 1], af[mi], bq + 2);
                    }
                }
            }
        }
    }
#pragma unroll
    for (int mi = 0; mi < 5; mi++)
#pragma unroll
        for (int p = 0; p < 4; p++)
#pragma unroll
            for (int hf = 0; hf < 2; hf++) {
                int orow = wm * 80 + mi * 16 + hf * 8 + (lane >> 2);
                int n = nb * 128 + wn * 32 + p * 8 + 2 * (lane & 3);
                float v0 = ap[mi][p][hf * 2 + 0];
                float v1 = ap[mi][p][hf * 2 + 1];
                if (orow < 64) {
                    __half* o = orow < 32 ? d_fp : d_gp;
                    int oo = orow & 31;
                    float bz = orow < 32 ? fb[oo] : gb[oo];
                    __half h, l;
                    split2h(v0 + bz, h, l);
                    o[((size_t)b * N + n) * 64 + oo] = h;
                    o[((size_t)b * N + n) * 64 + 32 + oo] = l;
                    split2h(v1 + bz, h, l);
                    o[((size_t)b * N + n + 1) * 64 + oo] = h;
                    o[((size_t)b * N + n + 1) * 64 + 32 + oo] = l;
                } else {
                    int c = orow - 64;
                    float bz = hb[c];
                    __half2 hv = __floats2half2_rn(v0 + bz, v1 + bz);
                    *(__half2*)&d_h[((size_t)b * C + c) * N + n] = hv;
                }
            }
}

// ---------------- pass 1: Z_j via HMMA, 3-term, p-outer (exp hidden under MMA), g-frags hoisted ----------------
// grid (32 jb, 8 b), 256 threads, dyn smem 62464
__global__ __launch_bounds__(256, 1) void k_zsum() {
    extern __shared__ char sm[];
    const int SGH = 0, SGL = 10240;
    const int SFH[2] = {20480, 40960}, SFL[2] = {30720, 51200};
    const int SZ = 61440;
    uint32_t sb = smem_u32(sm);
    int tid = threadIdx.x, lane = tid & 31, w = tid >> 5;
    int jb = blockIdx.x, b = blockIdx.y;
    int wj = w & 3, wi2 = w >> 2;

    for (int t = tid; t < 1024; t += 256) {
        int row = t >> 3, p = t & 7;
        uint4 v = ((const uint4*)d_gp)[(size_t)(b * N + jb * 128 + row) * 8 + p];
        *(uint4*)(sm + (p < 4 ? SGH + row * 80 + p * 16 : SGL + row * 80 + (p - 4) * 16)) = v;
    }
    for (int t = tid; t < 1024; t += 256) {
        int row = t >> 3, p = t & 7;
        const char* src = (const char*)d_fp + ((size_t)(b * N + row) * 8 + p) * 16;
        cp16(sb + (p < 4 ? SFH[0] + row * 80 + p * 16 : SFL[0] + row * 80 + (p - 4) * 16), src);
    }
    CP_COMMIT();
    __syncthreads();

    // hoist A-frags (g is fixed for the whole block): [jtile][hl][k16]
    uint32_t ga[2][2][2][4];
#pragma unroll
    for (int jt = 0; jt < 2; jt++)
#pragma unroll
        for (int k16 = 0; k16 < 2; k16++) {
            ldsm4(ga[jt][0][k16], sb + SGH + (wj * 32 + jt * 16 + (lane & 15)) * 80 + k16 * 32 + (lane >> 4) * 16);
            ldsm4(ga[jt][1][k16], sb + SGL + (wj * 32 + jt * 16 + (lane & 15)) * 80 + k16 * 32 + (lane >> 4) * 16);
        }

    float zacc[4] = {0.f, 0.f, 0.f, 0.f};
    for (int ibt = 0; ibt < 32; ibt++) {
        int cur = ibt & 1;
        __syncthreads();
        if (ibt < 31) {
            int nxt = 1 - cur;
            for (int t = tid; t < 1024; t += 256) {
                int row = t >> 3, p = t & 7;
                const char* src = (const char*)d_fp + ((size_t)(b * N + (ibt + 1) * 128 + row) * 8 + p) * 16;
                cp16(sb + (p < 4 ? SFH[nxt] + row * 80 + p * 16 : SFL[nxt] + row * 80 + (p - 4) * 16), src);
            }
        }
        CP_COMMIT();
        CP_WAIT1();
        __syncthreads();

#pragma unroll
        for (int p = 0; p < 4; p++) {   // i cols: wi2*64 + p*16 (+0/+8) — 64 rows per warp-half
            float t0[4] = {}, t1[4] = {}, t2[4] = {}, t3[4] = {};
#pragma unroll
            for (int k16 = 0; k16 < 2; k16++) {
                uint32_t baddr = (wi2 * 64 + p * 16 + ((lane >> 4) & 1) * 8 + (lane & 7)) * 80
                                 + k16 * 32 + ((lane >> 3) & 1) * 16;
                uint32_t bh[4];
                ldsm4(bh, sb + SFH[cur] + baddr);
                mma_f16(t0, ga[0][0][k16], bh); mma_f16(t1, ga[0][0][k16], bh + 2);
                mma_f16(t2, ga[1][0][k16], bh); mma_f16(t3, ga[1][0][k16], bh + 2);
                mma_f16(t0, ga[0][1][k16], bh); mma_f16(t1, ga[0][1][k16], bh + 2);
                mma_f16(t2, ga[1][1][k16], bh); mma_f16(t3, ga[1][1][k16], bh + 2);
                uint32_t bl[4];
                ldsm4(bl, sb + SFL[cur] + baddr);
                mma_f16(t0, ga[0][0][k16], bl); mma_f16(t1, ga[0][0][k16], bl + 2);
                mma_f16(t2, ga[1][0][k16], bl); mma_f16(t3, ga[1][0][k16], bl + 2);
            }
            zacc[0] += __expf(t0[0]) + __expf(t0[1]) + __expf(t1[0]) + __expf(t1[1]);
            zacc[1] += __expf(t0[2]) + __expf(t0[3]) + __expf(t1[2]) + __expf(t1[3]);
            zacc[2] += __expf(t2[0]) + __expf(t2[1]) + __expf(t3[0]) + __expf(t3[1]);
            zacc[3] += __expf(t2[2]) + __expf(t2[3]) + __expf(t3[2]) + __expf(t3[3]);
        }
    }
#pragma unroll
    for (int m = 0; m < 4; m++) {
        float v = zacc[m];
        v += __shfl_xor_sync(0xffffffffu, v, 1);
        v += __shfl_xor_sync(0xffffffffu, v, 2);
        if ((lane & 3) == 0) {
            int jloc = wj * 32 + (m >> 1) * 16 + (m & 1) * 8 + (lane >> 2);
            *(float*)(sm + SZ + (wi2 * 128 + jloc) * 4) = v;
        }
    }
    __syncthreads();
    if (tid < 128) {
        float z = *(float*)(sm + SZ + tid * 4) + *(float*)(sm + SZ + (128 + tid) * 4);
        d_rz[b * N + jb * 128 + tid] = 1.f / z;
    }
}

// ---------------- pass 2 (group-split): S p-outer w/ interleaved exp -> E -> O, out = O + x ----------------
// grid (32 ib, 8 b), 256 threads (2 groups x 4 warps), dyn smem 231424
__global__ __launch_bounds__(256, 1) void k_out(const float* __restrict__ x, float* __restrict__ out) {
    extern __shared__ char sm[];
    const int SFH = 0, SFL = 10240, SGH = 20480, SGL = 30720;
    const int SE = 40960;                       // E [128][272] group-local halves
    const int SHB[2] = {75776, 145408};         // 2 x H [256][272]
    const int SR = 215040;                      // rz for whole batch b: 16KB
    uint32_t sb = smem_u32(sm);
    int tid = threadIdx.x, lane = tid & 31, w = tid >> 5;
    int ib = blockIdx.x, b = blockIdx.y;
    int grp = w >> 2, wq = w & 3;
    int i0 = grp * 64 + wq * 16;    // S phase: this warp's 16 i rows

    // prologue: cp g(0), H(0), H(1); direct f + rz
    for (int t = tid; t < 1024; t += 256) {
        int row = t >> 3, p = t & 7;
        const char* src = (const char*)d_gp + ((size_t)(b * N + row) * 8 + p) * 16;
        cp16(sb + (p < 4 ? SGH + row * 80 + p * 16 : SGL + row * 80 + (p - 4) * 16), src);
    }
    CP_COMMIT();
    for (int t = tid; t < 4096; t += 256) {
        int row = t >> 4, u = t & 15;
        cp16(sb + SHB[0] + row * 272 + u * 16,
             (const char*)d_h + ((size_t)(b * C + row) * N + u * 8) * 2);
    }
    CP_COMMIT();
    for (int t = tid; t < 4096; t += 256) {
        int row = t >> 4, u = t & 15;
        cp16(sb + SHB[1] + row * 272 + u * 16,
             (const char*)d_h + ((size_t)(b * C + row) * N + 128 + u * 8) * 2);
    }
    CP_COMMIT();
    for (int t = tid; t < 1024; t += 256) {
        int row = t >> 3, p = t & 7;
        uint4 v = ((const uint4*)d_fp)[(size_t)(b * N + ib * 128 + row) * 8 + p];
        *(uint4*)(sm + (p < 4 ? SFH + row * 80 + p * 16 : SFL + row * 80 + (p - 4) * 16)) = v;
    }
    for (int t = tid; t < 1024; t += 256)
        ((float4*)(sm + SR))[t] = ((const float4*)(d_rz + (size_t)b * N))[t];
    __syncthreads();

    // hoist f A-frags (constant across all jb)
    uint32_t fah[2][4], fal[2][4];
#pragma unroll
    for (int k16 = 0; k16 < 2; k16++) {
        ldsm4(fah[k16], sb + SFH + (i0 + (lane & 15)) * 80 + k16 * 32 + (lane >> 4) * 16);
        ldsm4(fal[k16], sb + SFL + (i0 + (lane & 15)) * 80 + k16 * 32 + (lane >> 4) * 16);
    }

    float ao[4][8][4] = {};   // O: c = wq*64 + mi*16.., i = grp*64 + n*8..
    for (int jb = 0; jb < 32; jb++) {
        if (jb == 31) { CP_WAIT0(); } else { CP_WAIT1(); }  // tail: drain g(31) too
        __syncthreads();       // bar1: g/H visible, prev O done reading E

        // --- S (p-outer) with exp/pack/STS interleaved per tile-pair ---
        int irow = i0 + (lane >> 2);
#pragma unroll
        for (int p = 0; p < 8; p++) {
            float t0[4] = {}, t1[4] = {};
#pragma unroll
            for (int k16 = 0; k16 < 2; k16++) {
                uint32_t baddr = (p * 16 + ((lane >> 4) & 1) * 8 + (lane & 7)) * 80
                                 + k16 * 32 + ((lane >> 3) & 1) * 16;
                uint32_t bh[4];
                ldsm4(bh, sb + SGH + baddr);
                mma_f16(t0, fah[k16], bh); mma_f16(t1, fah[k16], bh + 2);
                mma_f16(t0, fal[k16], bh); mma_f16(t1, fal[k16], bh + 2);
                uint32_t bl[4];
                ldsm4(bl, sb + SGL + baddr);
                mma_f16(t0, fah[k16], bl); mma_f16(t1, fah[k16], bl + 2);
            }
            int jc0 = p * 16 + 2 * (lane & 3);
            float2 rz0 = *(float2*)(sm + SR + (jb * 128 + jc0) * 4);
            float2 rz1 = *(float2*)(sm + SR + (jb * 128 + jc0 + 8) * 4);
            __half2 h00 = __floats2half2_rn(__expf(t0[0]) * rz0.x, __expf(t0[1]) * rz0.y);
            __half2 h01 = __floats2half2_rn(__expf(t0[2]) * rz0.x, __expf(t0[3]) * rz0.y);
            __half2 h10 = __floats2half2_rn(__expf(t1[0]) * rz1.x, __expf(t1[1]) * rz1.y);
            __half2 h11 = __floats2half2_rn(__expf(t1[2]) * rz1.x, __expf(t1[3]) * rz1.y);
            *(uint32_t*)(sm + SE + irow * 272 + jc0 * 2)             = *(uint32_t*)&h00;
            *(uint32_t*)(sm + SE + (irow + 8) * 272 + jc0 * 2)       = *(uint32_t*)&h01;
            *(uint32_t*)(sm + SE + irow * 272 + (jc0 + 8) * 2)       = *(uint32_t*)&h10;
            *(uint32_t*)(sm + SE + (irow + 8) * 272 + (jc0 + 8) * 2) = *(uint32_t*)&h11;
        }
        BAR_GRP(grp + 1);      // group-local: our E half complete

        // --- O: A = H rows c (wq*64..+64), B = E rows i (grp*64..+64), k = j ---
        int SH = SHB[jb & 1];
#pragma unroll
        for (int k16 = 0; k16 < 8; k16++) {
            uint32_t af[4][4];
#pragma unroll
            for (int mi = 0; mi < 4; mi++)
                ldsm4(af[mi], sb + SH + (wq * 64 + mi * 16 + (lane & 15)) * 272 + k16 * 32 + (lane >> 4) * 16);
#pragma unroll
            for (int p2 = 0; p2 < 4; p2++) {
                uint32_t bq[4];
                ldsm4(bq, sb + SE + (grp * 64 + p2 * 16 + ((lane >> 4) & 1) * 8 + (lane & 7)) * 272
                          + k16 * 32 + ((lane >> 3) & 1) * 16);
#pragma unroll
                for (int mi = 0; mi < 4; mi++) {
                    mma_f16(ao[mi][2 * p2],     af[mi], bq);
                    mma_f16(ao[mi][2 * p2 + 1], af[mi], bq + 2);
                }
            }
        }
        __syncthreads();       // bar2: O reads of g/E/H(cur) done; buffers reusable

        if (jb < 31) {
            for (int t = tid; t < 1024; t += 256) {
                int row = t >> 3, p = t & 7;
                const char* src = (const char*)d_gp + ((size_t)(b * N + (jb + 1) * 128 + row) * 8 + p) * 16;
                cp16(sb + (p < 4 ? SGH + row * 80 + p * 16 : SGL + row * 80 + (p - 4) * 16), src);
            }
            CP_COMMIT();
        }
        if (jb < 30) {
            for (int t = tid; t < 4096; t += 256) {
                int row = t >> 4, u = t & 15;
                cp16(sb + SHB[jb & 1] + row * 272 + u * 16,
                     (const char*)d_h + ((size_t)(b * C + row) * N + (jb + 2) * 128 + u * 8) * 2);
            }
            CP_COMMIT();
        }
    }

    // epilogue: out[b][c][i] = O + x
#pragma unroll
    for (int mi = 0; mi < 4; mi++)
#pragma unroll
        for (int n = 0; n < 8; n++) {
            int c = wq * 64 + mi * 16 + (lane >> 2);
            int icol = ib * 128 + grp * 64 + n * 8 + 2 * (lane & 3);
            size_t idx = (size_t)(b * C + c) * N + icol;
            float2 xv = *(const float2*)&x[idx];
            *(float2*)&out[idx] = make_float2(ao[mi][n][0] + xv.x, ao[mi][n][1] + xv.y);
            idx += (size_t)8 * N;
            xv = *(const float2*)&x[idx];
            *(float2*)&out[idx] = make_float2(ao[mi][n][2] + xv.x, ao[mi][n][3] + xv.y);
        }
}

// ---------------- launch ----------------
extern "C" void kernel_launch(void* const* d_in, const int* in_sizes, int n_in,
                              void* d_out, int out_size) {
    const float* x  = (const float*)d_in[0];
    const float* fw = (const float*)d_in[1];
    const float* fb = (const float*)d_in[2];
    const float* gw = (const float*)d_in[3];
    const float* gb = (const float*)d_in[4];
    const float* hw = (const float*)d_in[5];
    const float* hb = (const float*)d_in[6];
    float* out = (float*)d_out;

    const int SM_P = 71680;
    const int SM_Z = 62464;
    const int SM_O = 231424;
    cudaFuncSetAttribute(k_proj, cudaFuncAttributeMaxDynamicSharedMemorySize, SM_P);
    cudaFuncSetAttribute(k_zsum, cudaFuncAttributeMaxDynamicSharedMemorySize, SM_Z);
    cudaFuncSetAttribute(k_out,  cudaFuncAttributeMaxDynamicSharedMemorySize, SM_O);

    k_prep<<<160, 512>>>(fw, gw, hw);
    k_proj<<<dim3(32, 8), 512, SM_P>>>(x, fb, gb, hb);
    k_zsum<<<dim3(32, 8), 256, SM_Z>>>();
    k_out<<<dim3(32, 8), 256, SM_O>>>(x, out);
}

// round 15
// speedup vs baseline: 6.1250x; 1.0327x over previous
#include <cuda_runtime.h>
#include <cuda_fp16.h>
#include <cstdint>
#include <math.h>

#define Bn 8
#define C  256
#define N  4096

// ---------------- scratch ----------------
__device__ __half d_fp[Bn * N * 64];            // f packed fp16 [b][n][hi k0..31 | lo k0..31]
__device__ __half d_gp[Bn * N * 64];            // g packed
__device__ __half d_h [(size_t)Bn * C * N];     // H = h_w x + h_b, fp16 [b][c][j] (NOT Z-scaled)
__device__ __half d_wh[320 * 256];              // W = [fw;gw;hw] split hi
__device__ __half d_wl[320 * 256];              // W split lo
__device__ float d_rz[Bn * N];                  // 1/Z_j

// ---------------- helpers ----------------
__device__ __forceinline__ uint32_t smem_u32(const void* p) {
    uint32_t a;
    asm("{ .reg .u64 t; cvta.to.shared.u64 t, %1; cvt.u32.u64 %0, t; }" : "=r"(a) : "l"(p));
    return a;
}
__device__ __forceinline__ void ldsm4(uint32_t* r, uint32_t a) {
    asm volatile("ldmatrix.sync.aligned.m8n8.x4.shared.b16 {%0,%1,%2,%3}, [%4];"
        : "=r"(r[0]), "=r"(r[1]), "=r"(r[2]), "=r"(r[3]) : "r"(a));
}
__device__ __forceinline__ void mma_f16(float* d, const uint32_t* a, const uint32_t* b) {
    asm volatile("mma.sync.aligned.m16n8k16.row.col.f32.f16.f16.f32 "
        "{%0,%1,%2,%3}, {%4,%5,%6,%7}, {%8,%9}, {%0,%1,%2,%3};"
        : "+f"(d[0]), "+f"(d[1]), "+f"(d[2]), "+f"(d[3])
        : "r"(a[0]), "r"(a[1]), "r"(a[2]), "r"(a[3]), "r"(b[0]), "r"(b[1]));
}
__device__ __forceinline__ void split2h(float v, __half& h, __half& l) {
    h = __float2half_rn(v);
    l = __float2half_rn(v - __half2float(h));
}
__device__ __forceinline__ void cp16(uint32_t dst, const void* src) {
    asm volatile("cp.async.cg.shared.global [%0], [%1], 16;" :: "r"(dst), "l"(src));
}
#define CP_COMMIT() asm volatile("cp.async.commit_group;" ::: "memory")
#define CP_WAIT0()  asm volatile("cp.async.wait_group 0;" ::: "memory")
#define CP_WAIT1()  asm volatile("cp.async.wait_group 1;" ::: "memory")
#define BAR_GRP256(id) asm volatile("bar.sync %0, 256;" :: "r"(id) : "memory")

// ---------------- W pre-split: [fw;gw;hw] -> packed fp16 hi/lo ----------------
__global__ __launch_bounds__(512) void k_prep(const float* __restrict__ fw,
                                              const float* __restrict__ gw,
                                              const float* __restrict__ hw) {
    int idx = blockIdx.x * 512 + threadIdx.x;   // 81920
    int row = idx >> 8, cc = idx & 255;
    const float* wp = row < 32 ? fw + row * 256
                     : row < 64 ? gw + (row - 32) * 256
                                : hw + (row - 64) * 256;
    __half h, l;
    split2h(wp[cc], h, l);
    d_wh[idx] = h;
    d_wl[idx] = l;
}

// ---------------- merged projections via 3-term fp16 HMMA, W tiles via cp.async ----------------
// grid (32 nb, 8 b), 512 threads, dyn smem 71680
__global__ __launch_bounds__(512, 1) void k_proj(
    const float* __restrict__ x,
    const float* __restrict__ fb, const float* __restrict__ gb, const float* __restrict__ hb) {
    extern __shared__ char sm[];
    const int WH = 0, WL = 25600, XH = 51200, XL = 61440;
    uint32_t sb = smem_u32(sm);
    int tid = threadIdx.x, lane = tid & 31, w = tid >> 5;
    int nb = blockIdx.x, b = blockIdx.y;
    int wm = w & 3, wn = w >> 2;
    float ap[5][4][4] = {};

    for (int c0 = 0; c0 < 256; c0 += 32) {
        __syncthreads();
        for (int t = tid; t < 1280; t += 512) {
            int row = t >> 2, p = t & 3;
            cp16(sb + WH + row * 80 + p * 16, (const char*)d_wh + (row * 256 + c0 + p * 8) * 2);
            cp16(sb + WL + row * 80 + p * 16, (const char*)d_wl + (row * 256 + c0 + p * 8) * 2);
        }
        CP_COMMIT();
        for (int idx = tid; idx < 4096; idx += 512) {
            int cc = idx >> 7, n = idx & 127;
            __half h, l;
            split2h(x[((size_t)b * 256 + c0 + cc) * 4096 + nb * 128 + n], h, l);
            *(__half*)(sm + XH + n * 80 + cc * 2) = h;
            *(__half*)(sm + XL + n * 80 + cc * 2) = l;
        }
        CP_WAIT0();
        __syncthreads();
#pragma unroll
        for (int term = 0; term < 3; term++) {
            int Ab = term == 2 ? WL : WH;
            int Bb = term == 1 ? XL : XH;
#pragma unroll
            for (int k16 = 0; k16 < 2; k16++) {
                uint32_t af[5][4];
#pragma unroll
                for (int mi = 0; mi < 5; mi++)
                    ldsm4(af[mi], sb + Ab + (wm * 80 + mi * 16 + (lane & 15)) * 80 + k16 * 32 + (lane >> 4) * 16);
#pragma unroll
                for (int p = 0; p < 2; p++) {
                    uint32_t bq[4];
                    ldsm4(bq, sb + Bb + (wn * 32 + p * 16 + ((lane >> 4) & 1) * 8 + (lane & 7)) * 80
                              + k16 * 32 + ((lane >> 3) & 1) * 16);
#pragma unroll
                    for (int mi = 0; mi < 5; mi++) {
                        mma_f16(ap[mi][2 * p],     af[mi], bq);
                        mma_f16(ap[mi][2 * p + 1], af[mi], bq + 2);
                    }
                }
            }
        }
    }
#pragma unroll
    for (int mi = 0; mi < 5; mi++)
#pragma unroll
        for (int p = 0; p < 4; p++)
#pragma unroll
            for (int hf = 0; hf < 2; hf++) {
                int orow = wm * 80 + mi * 16 + hf * 8 + (lane >> 2);
                int n = nb * 128 + wn * 32 + p * 8 + 2 * (lane & 3);
                float v0 = ap[mi][p][hf * 2 + 0];
                float v1 = ap[mi][p][hf * 2 + 1];
                if (orow < 64) {
                    __half* o = orow < 32 ? d_fp : d_gp;
                    int oo = orow & 31;
                    float bz = orow < 32 ? fb[oo] : gb[oo];
                    __half h, l;
                    split2h(v0 + bz, h, l);
                    o[((size_t)b * N + n) * 64 + oo] = h;
                    o[((size_t)b * N + n) * 64 + 32 + oo] = l;
                    split2h(v1 + bz, h, l);
                    o[((size_t)b * N + n + 1) * 64 + oo] = h;
                    o[((size_t)b * N + n + 1) * 64 + 32 + oo] = l;
                } else {
                    int c = orow - 64;
                    float bz = hb[c];
                    __half2 hv = __floats2half2_rn(v0 + bz, v1 + bz);
                    *(__half2*)&d_h[((size_t)b * C + c) * N + n] = hv;
                }
            }
}

// ---------------- pass 1: Z_j via HMMA, 3-term, p-outer, g-frags hoisted ----------------
// grid (32 jb, 8 b), 256 threads, dyn smem 62464
__global__ __launch_bounds__(256, 1) void k_zsum() {
    extern __shared__ char sm[];
    const int SGH = 0, SGL = 10240;
    const int SFH[2] = {20480, 40960}, SFL[2] = {30720, 51200};
    const int SZ = 61440;
    uint32_t sb = smem_u32(sm);
    int tid = threadIdx.x, lane = tid & 31, w = tid >> 5;
    int jb = blockIdx.x, b = blockIdx.y;
    int wj = w & 3, wi2 = w >> 2;

    for (int t = tid; t < 1024; t += 256) {
        int row = t >> 3, p = t & 7;
        uint4 v = ((const uint4*)d_gp)[(size_t)(b * N + jb * 128 + row) * 8 + p];
        *(uint4*)(sm + (p < 4 ? SGH + row * 80 + p * 16 : SGL + row * 80 + (p - 4) * 16)) = v;
    }
    for (int t = tid; t < 1024; t += 256) {
        int row = t >> 3, p = t & 7;
        const char* src = (const char*)d_fp + ((size_t)(b * N + row) * 8 + p) * 16;
        cp16(sb + (p < 4 ? SFH[0] + row * 80 + p * 16 : SFL[0] + row * 80 + (p - 4) * 16), src);
    }
    CP_COMMIT();
    __syncthreads();

    uint32_t ga[2][2][2][4];
#pragma unroll
    for (int jt = 0; jt < 2; jt++)
#pragma unroll
        for (int k16 = 0; k16 < 2; k16++) {
            ldsm4(ga[jt][0][k16], sb + SGH + (wj * 32 + jt * 16 + (lane & 15)) * 80 + k16 * 32 + (lane >> 4) * 16);
            ldsm4(ga[jt][1][k16], sb + SGL + (wj * 32 + jt * 16 + (lane & 15)) * 80 + k16 * 32 + (lane >> 4) * 16);
        }

    float zacc[4] = {0.f, 0.f, 0.f, 0.f};
    for (int ibt = 0; ibt < 32; ibt++) {
        int cur = ibt & 1;
        __syncthreads();
        if (ibt < 31) {
            int nxt = 1 - cur;
            for (int t = tid; t < 1024; t += 256) {
                int row = t >> 3, p = t & 7;
                const char* src = (const char*)d_fp + ((size_t)(b * N + (ibt + 1) * 128 + row) * 8 + p) * 16;
                cp16(sb + (p < 4 ? SFH[nxt] + row * 80 + p * 16 : SFL[nxt] + row * 80 + (p - 4) * 16), src);
            }
        }
        CP_COMMIT();
        CP_WAIT1();
        __syncthreads();

#pragma unroll
        for (int p = 0; p < 4; p++) {
            float t0[4] = {}, t1[4] = {}, t2[4] = {}, t3[4] = {};
#pragma unroll
            for (int k16 = 0; k16 < 2; k16++) {
                uint32_t baddr = (wi2 * 64 + p * 16 + ((lane >> 4) & 1) * 8 + (lane & 7)) * 80
                                 + k16 * 32 + ((lane >> 3) & 1) * 16;
                uint32_t bh[4];
                ldsm4(bh, sb + SFH[cur] + baddr);
                mma_f16(t0, ga[0][0][k16], bh); mma_f16(t1, ga[0][0][k16], bh + 2);
                mma_f16(t2, ga[1][0][k16], bh); mma_f16(t3, ga[1][0][k16], bh + 2);
                mma_f16(t0, ga[0][1][k16], bh); mma_f16(t1, ga[0][1][k16], bh + 2);
                mma_f16(t2, ga[1][1][k16], bh); mma_f16(t3, ga[1][1][k16], bh + 2);
                uint32_t bl[4];
                ldsm4(bl, sb + SFL[cur] + baddr);
                mma_f16(t0, ga[0][0][k16], bl); mma_f16(t1, ga[0][0][k16], bl + 2);
                mma_f16(t2, ga[1][0][k16], bl); mma_f16(t3, ga[1][0][k16], bl + 2);
            }
            zacc[0] += __expf(t0[0]) + __expf(t0[1]) + __expf(t1[0]) + __expf(t1[1]);
            zacc[1] += __expf(t0[2]) + __expf(t0[3]) + __expf(t1[2]) + __expf(t1[3]);
            zacc[2] += __expf(t2[0]) + __expf(t2[1]) + __expf(t3[0]) + __expf(t3[1]);
            zacc[3] += __expf(t2[2]) + __expf(t2[3]) + __expf(t3[2]) + __expf(t3[3]);
        }
    }
#pragma unroll
    for (int m = 0; m < 4; m++) {
        float v = zacc[m];
        v += __shfl_xor_sync(0xffffffffu, v, 1);
        v += __shfl_xor_sync(0xffffffffu, v, 2);
        if ((lane & 3) == 0) {
            int jloc = wj * 32 + (m >> 1) * 16 + (m & 1) * 8 + (lane >> 2);
            *(float*)(sm + SZ + (wi2 * 128 + jloc) * 4) = v;
        }
    }
    __syncthreads();
    if (tid < 128) {
        float z = *(float*)(sm + SZ + tid * 4) + *(float*)(sm + SZ + (128 + tid) * 4);
        d_rz[b * N + jb * 128 + tid] = 1.f / z;
    }
}

// ---------------- pass 2: 512 threads, 2 groups x 8 warps; S -> exp -> E(group) -> O ----------------
// grid (32 ib, 8 b), 512 threads, dyn smem 231424
__global__ __launch_bounds__(512, 1) void k_out(const float* __restrict__ x, float* __restrict__ out) {
    extern __shared__ char sm[];
    const int SFH = 0, SFL = 10240, SGH = 20480, SGL = 30720;
    const int SE = 40960;                       // E [128][272] group-local halves
    const int SHB[2] = {75776, 145408};         // 2 x H [256][272]
    const int SR = 215040;                      // rz for whole batch b: 16KB
    uint32_t sb = smem_u32(sm);
    int tid = threadIdx.x, lane = tid & 31, w = tid >> 5;
    int ib = blockIdx.x, b = blockIdx.y;
    int grp = w >> 3, wg = w & 7;
    int i0 = grp * 64 + (wg & 3) * 16;   // S phase: this warp's 16 i rows
    int jq = wg >> 2;                    // S phase: j half

    // prologue: cp g(0), H(0), H(1); direct f + rz
    for (int t = tid; t < 1024; t += 512) {
        int row = t >> 3, p = t & 7;
        const char* src = (const char*)d_gp + ((size_t)(b * N + row) * 8 + p) * 16;
        cp16(sb + (p < 4 ? SGH + row * 80 + p * 16 : SGL + row * 80 + (p - 4) * 16), src);
    }
    CP_COMMIT();
    for (int t = tid; t < 4096; t += 512) {
        int row = t >> 4, u = t & 15;
        cp16(sb + SHB[0] + row * 272 + u * 16,
             (const char*)d_h + ((size_t)(b * C + row) * N + u * 8) * 2);
    }
    CP_COMMIT();
    for (int t = tid; t < 4096; t += 512) {
        int row = t >> 4, u = t & 15;
        cp16(sb + SHB[1] + row * 272 + u * 16,
             (const char*)d_h + ((size_t)(b * C + row) * N + 128 + u * 8) * 2);
    }
    CP_COMMIT();
    for (int t = tid; t < 1024; t += 512) {
        int row = t >> 3, p = t & 7;
        uint4 v = ((const uint4*)d_fp)[(size_t)(b * N + ib * 128 + row) * 8 + p];
        *(uint4*)(sm + (p < 4 ? SFH + row * 80 + p * 16 : SFL + row * 80 + (p - 4) * 16)) = v;
    }
    for (int t = tid; t < 1024; t += 512)
        ((float4*)(sm + SR))[t] = ((const float4*)(d_rz + (size_t)b * N))[t];
    __syncthreads();

    // hoist f A-frags (constant across all jb)
    uint32_t fah[2][4], fal[2][4];
#pragma unroll
    for (int k16 = 0; k16 < 2; k16++) {
        ldsm4(fah[k16], sb + SFH + (i0 + (lane & 15)) * 80 + k16 * 32 + (lane >> 4) * 16);
        ldsm4(fal[k16], sb + SFL + (i0 + (lane & 15)) * 80 + k16 * 32 + (lane >> 4) * 16);
    }

    float ao[2][8][4] = {};   // O: c = wg*32 + mi*16.., i = grp*64 + n*8..
    for (int jb = 0; jb < 32; jb++) {
        if (jb == 31) { CP_WAIT0(); } else { CP_WAIT1(); }  // tail: drain g(31) too
        __syncthreads();       // bar1: g/H visible, prev O done reading E

        // --- S (p-outer, 16i x 64j per warp) with exp/pack/STS interleaved ---
        int irow = i0 + (lane >> 2);
#pragma unroll
        for (int p = 0; p < 4; p++) {
            float t0[4] = {}, t1[4] = {};
#pragma unroll
            for (int k16 = 0; k16 < 2; k16++) {
                uint32_t baddr = (jq * 64 + p * 16 + ((lane >> 4) & 1) * 8 + (lane & 7)) * 80
                                 + k16 * 32 + ((lane >> 3) & 1) * 16;
                uint32_t bh[4];
                ldsm4(bh, sb + SGH + baddr);
                mma_f16(t0, fah[k16], bh); mma_f16(t1, fah[k16], bh + 2);
                mma_f16(t0, fal[k16], bh); mma_f16(t1, fal[k16], bh + 2);
                uint32_t bl[4];
                ldsm4(bl, sb + SGL + baddr);
                mma_f16(t0, fah[k16], bl); mma_f16(t1, fah[k16], bl + 2);
            }
            int jc0 = jq * 64 + p * 16 + 2 * (lane & 3);
            float2 rz0 = *(float2*)(sm + SR + (jb * 128 + jc0) * 4);
            float2 rz1 = *(float2*)(sm + SR + (jb * 128 + jc0 + 8) * 4);
            __half2 h00 = __floats2half2_rn(__expf(t0[0]) * rz0.x, __expf(t0[1]) * rz0.y);
            __half2 h01 = __floats2half2_rn(__expf(t0[2]) * rz0.x, __expf(t0[3]) * rz0.y);
            __half2 h10 = __floats2half2_rn(__expf(t1[0]) * rz1.x, __expf(t1[1]) * rz1.y);
            __half2 h11 = __floats2half2_rn(__expf(t1[2]) * rz1.x, __expf(t1[3]) * rz1.y);
            *(uint32_t*)(sm + SE + irow * 272 + jc0 * 2)             = *(uint32_t*)&h00;
            *(uint32_t*)(sm + SE + (irow + 8) * 272 + jc0 * 2)       = *(uint32_t*)&h01;
            *(uint32_t*)(sm + SE + irow * 272 + (jc0 + 8) * 2)       = *(uint32_t*)&h10;
            *(uint32_t*)(sm + SE + (irow + 8) * 272 + (jc0 + 8) * 2) = *(uint32_t*)&h11;
        }
        BAR_GRP256(grp + 1);   // group-local (8 warps): our E half complete

        // --- O: A = H rows c (wg*32..+32), B = E rows i (grp*64..+64), k = j ---
        int SH = SHB[jb & 1];
#pragma unroll
        for (int k16 = 0; k16 < 8; k16++) {
            uint32_t af[2][4];
#pragma unroll
            for (int mi = 0; mi < 2; mi++)
                ldsm4(af[mi], sb + SH + (wg * 32 + mi * 16 + (lane & 15)) * 272 + k16 * 32 + (lane >> 4) * 16);
#pragma unroll
            for (int p2 = 0; p2 < 4; p2++) {
                uint32_t bq[4];
                ldsm4(bq, sb + SE + (grp * 64 + p2 * 16 + ((lane >> 4) & 1) * 8 + (lane & 7)) * 272
                          + k16 * 32 + ((lane >> 3) & 1) * 16);
#pragma unroll
                for (int mi = 0; mi < 2; mi++) {
                    mma_f16(ao[mi][2 * p2],     af[mi], bq);
                    mma_f16(ao[mi][2 * p2 + 1], af[mi], bq + 2);
                }
            }
        }
        __syncthreads();       // bar2: O reads of g/E/H(cur) done; buffers reusable

        if (jb < 31) {
            for (int t = tid; t < 1024; t += 512) {
                int row = t >> 3, p = t & 7;
                const char* src = (const char*)d_gp + ((size_t)(b * N + (jb + 1) * 128 + row) * 8 + p) * 16;
                cp16(sb + (p < 4 ? SGH + row * 80 + p * 16 : SGL + row * 80 + (p - 4) * 16), src);
            }
            CP_COMMIT();
        }
        if (jb < 30) {
            for (int t = tid; t < 4096; t += 512) {
                int row = t >> 4, u = t & 15;
                cp16(sb + SHB[jb & 1] + row * 272 + u * 16,
                     (const char*)d_h + ((size_t)(b * C + row) * N + (jb + 2) * 128 + u * 8) * 2);
            }
            CP_COMMIT();
        }
    }

    // epilogue: out[b][c][i] = O + x
#pragma unroll
    for (int mi = 0; mi < 2; mi++)
#pragma unroll
        for (int n = 0; n < 8; n++) {
            int c = wg * 32 + mi * 16 + (lane >> 2);
            int icol = ib * 128 + grp * 64 + n * 8 + 2 * (lane & 3);
            size_t idx = (size_t)(b * C + c) * N + icol;
            float2 xv = *(const float2*)&x[idx];
            *(float2*)&out[idx] = make_float2(ao[mi][n][0] + xv.x, ao[mi][n][1] + xv.y);
            idx += (size_t)8 * N;
            xv = *(const float2*)&x[idx];
            *(float2*)&out[idx] = make_float2(ao[mi][n][2] + xv.x, ao[mi][n][3] + xv.y);
        }
}

// ---------------- launch ----------------
extern "C" void kernel_launch(void* const* d_in, const int* in_sizes, int n_in,
                              void* d_out, int out_size) {
    const float* x  = (const float*)d_in[0];
    const float* fw = (const float*)d_in[1];
    const float* fb = (const float*)d_in[2];
    const float* gw = (const float*)d_in[3];
    const float* gb = (const float*)d_in[4];
    const float* hw = (const float*)d_in[5];
    const float* hb = (const float*)d_in[6];
    float* out = (float*)d_out;

    const int SM_P = 71680;
    const int SM_Z = 62464;
    const int SM_O = 231424;
    cudaFuncSetAttribute(k_proj, cudaFuncAttributeMaxDynamicSharedMemorySize, SM_P);
    cudaFuncSetAttribute(k_zsum, cudaFuncAttributeMaxDynamicSharedMemorySize, SM_Z);
    cudaFuncSetAttribute(k_out,  cudaFuncAttributeMaxDynamicSharedMemorySize, SM_O);

    k_prep<<<160, 512>>>(fw, gw, hw);
    k_proj<<<dim3(32, 8), 512, SM_P>>>(x, fb, gb, hb);
    k_zsum<<<dim3(32, 8), 256, SM_Z>>>();
    k_out<<<dim3(32, 8), 512, SM_O>>>(x, out);
}